// round 5
// baseline (speedup 1.0000x reference)
#include <cuda_runtime.h>
#include <cuda_bf16.h>
#include <stdint.h>

#define THREADS 512
#define TTILE 4           // T per CTA tile; 300 = 75*4
#define NTILE 75

// smem byte offsets
#define OFF_ZB    0         // 1600 f32
#define OFF_SCALE 6400      // 64 f32
#define OFF_SHIFT 6656      // 64 f32
#define OFF_CS    6912      // 75 f32 colsum
#define OFF_XH    7680      // 256 rows (c*4+t) x 64B (32 bf16 v, pad 0)
#define OFF_XL    24064
#define OFF_PAH   40448     // 96 rows (s*32+v) x 64B (32 bf16 w, pad 0)
#define OFF_PAL   46592
#define OFF_WH    52736     // 192 rows k=(s*64+c) x 144B (64 bf16 o + pad)
#define OFF_WL    80384
#define OFF_UH    108032    // 112 rows r=(t*25+w) x 400B (192 bf16 k + pad)
#define OFF_UL    152832
#define SMEM_TOTAL 197632

#define LDSM_X4(r, a) \
    asm volatile("ldmatrix.sync.aligned.m8n8.x4.shared.b16 {%0,%1,%2,%3}, [%4];" \
        : "=r"((r)[0]), "=r"((r)[1]), "=r"((r)[2]), "=r"((r)[3]) : "r"(a))
#define LDSM_X4T(r, a) \
    asm volatile("ldmatrix.sync.aligned.m8n8.x4.trans.shared.b16 {%0,%1,%2,%3}, [%4];" \
        : "=r"((r)[0]), "=r"((r)[1]), "=r"((r)[2]), "=r"((r)[3]) : "r"(a))
#define MMA(acc, a, b0, b1) \
    asm volatile("mma.sync.aligned.m16n8k16.row.col.f32.bf16.bf16.f32 " \
        "{%0,%1,%2,%3}, {%4,%5,%6,%7}, {%8,%9}, {%0,%1,%2,%3};" \
        : "+f"((acc)[0]), "+f"((acc)[1]), "+f"((acc)[2]), "+f"((acc)[3]) \
        : "r"((a)[0]), "r"((a)[1]), "r"((a)[2]), "r"((a)[3]), "r"(b0), "r"(b1))

__device__ __forceinline__ uint32_t cvta_smem(const void* p) {
    uint32_t a;
    asm("{ .reg .u64 t; cvta.to.shared.u64 t, %1; cvt.u32.u64 %0, t; }" : "=r"(a) : "l"(p));
    return a;
}
__device__ __forceinline__ void bf16split(float v, unsigned short& h, unsigned short& l) {
    __nv_bfloat16 hb = __float2bfloat16_rn(v);
    __nv_bfloat16 lb = __float2bfloat16_rn(v - __bfloat162float(hb));
    h = __bfloat16_as_ushort(hb);
    l = __bfloat16_as_ushort(lb);
}
// ldmatrix address: lanes 0-15 -> rows row0+0..15, lanes 16-31 same rows +16B col
__device__ __forceinline__ uint32_t lm_addr(uint32_t base, int row0, int colByte,
                                            int stride, int lane) {
    return base + (uint32_t)((row0 + (lane & 15)) * stride + colByte + (lane >> 4) * 16);
}

__global__ __launch_bounds__(THREADS, 1)
void stgcn_mma(const float* __restrict__ x,  const float* __restrict__ PA,
               const float* __restrict__ Wc, const float* __restrict__ bc,
               const float* __restrict__ gamma, const float* __restrict__ beta,
               const float* __restrict__ mean,  const float* __restrict__ var,
               float* __restrict__ out)
{
    extern __shared__ char sm[];
    const uint32_t sb = cvta_smem(sm);
    const int tid = threadIdx.x, wid = tid >> 5, lane = tid & 31;
    const int b = blockIdx.x & 63, tile = blockIdx.x >> 6;
    const int n = b >> 1, m = b & 1, t0 = tile * TTILE;

    // ---- zero X+PA regions (covers v/w padding) ----
    {
        uint4 z = make_uint4(0, 0, 0, 0);
        uint4* p = (uint4*)(sm + OFF_XH);          // X(h+l) + PA(h+l): 45056 B
        for (int i = tid; i < 45056 / 16; i += THREADS) p[i] = z;
    }
    if (tid < 75) {      // colsum[s][w] = sum_v PA[s][v][w]
        int s = tid / 25, w = tid - s * 25;
        float acc = 0.f;
        for (int v = 0; v < 25; v++) acc += PA[s * 625 + v * 25 + w];
        ((float*)(sm + OFF_CS))[tid] = acc;
    }
    if (tid < 64) {
        float sc = gamma[tid] * rsqrtf(var[tid] + 1e-5f);
        ((float*)(sm + OFF_SCALE))[tid] = sc;
        ((float*)(sm + OFF_SHIFT))[tid] = beta[tid] - mean[tid] * sc;
    }
    __syncthreads();

    // ---- fill X: rows c*4+t, cols v ----
    for (int i = tid; i < 64 * TTILE * 25; i += THREADS) {
        int c = i / (TTILE * 25), r = i - c * (TTILE * 25), t = r / 25, v = r - t * 25;
        float val = x[(((n * 64 + c) * 300 + (t0 + t)) * 25 + v) * 2 + m];
        unsigned short h, l; bf16split(val, h, l);
        int off = (c * TTILE + t) * 64 + v * 2;
        *(unsigned short*)(sm + OFF_XH + off) = h;
        *(unsigned short*)(sm + OFF_XL + off) = l;
    }
    // ---- fill PA: rows s*32+v, cols w ----
    for (int i = tid; i < 3 * 625; i += THREADS) {
        int s = i / 625, r = i - s * 625, v = r / 25, w = r - v * 25;
        unsigned short h, l; bf16split(PA[i], h, l);
        int off = (s * 32 + v) * 64 + w * 2;
        *(unsigned short*)(sm + OFF_PAH + off) = h;
        *(unsigned short*)(sm + OFF_PAL + off) = l;
    }
    // ---- fill W^T: rows k=s*64+c, cols o ----
    for (int i = tid; i < 192 * 64; i += THREADS) {
        int so = i >> 6, c = i & 63, s = so >> 6, o = so & 63;
        unsigned short h, l; bf16split(Wc[i], h, l);
        int off = (s * 64 + c) * 144 + o * 2;
        *(unsigned short*)(sm + OFF_WH + off) = h;
        *(unsigned short*)(sm + OFF_WL + off) = l;
    }
    // ---- zb[o][w] = sum_s bias[s*64+o]*colsum[s][w] ----
    for (int i = tid; i < 1600; i += THREADS) {
        int o = i / 25, w = i - o * 25;
        const float* cs = (const float*)(sm + OFF_CS);
        ((float*)(sm + OFF_ZB))[i] =
            bc[o] * cs[w] + bc[64 + o] * cs[25 + w] + bc[128 + o] * cs[50 + w];
    }
    __syncthreads();

    // ================= Stage 1: u_s = X * PA_s  (M=256, K=32, N=32) =================
    // warp wid owns rows wid*16..wid*16+15 (c = row>>2, t = row&3)
    {
        uint32_t Ah[2][4], Al[2][4];
        #pragma unroll
        for (int k16 = 0; k16 < 2; k16++) {
            LDSM_X4(Ah[k16], lm_addr(sb + OFF_XH, wid * 16, k16 * 32, 64, lane));
            LDSM_X4(Al[k16], lm_addr(sb + OFF_XL, wid * 16, k16 * 32, 64, lane));
        }
        for (int s = 0; s < 3; s++) {
            uint32_t Bh[2][8], Bl[2][8];
            #pragma unroll
            for (int k16 = 0; k16 < 2; k16++)
                #pragma unroll
                for (int n16 = 0; n16 < 2; n16++) {
                    LDSM_X4T(&Bh[k16][n16 * 4],
                        lm_addr(sb + OFF_PAH + s * 2048, k16 * 16, n16 * 32, 64, lane));
                    LDSM_X4T(&Bl[k16][n16 * 4],
                        lm_addr(sb + OFF_PAL + s * 2048, k16 * 16, n16 * 32, 64, lane));
                }
            float acc[4][4];
            #pragma unroll
            for (int j = 0; j < 4; j++)
                #pragma unroll
                for (int e = 0; e < 4; e++) acc[j][e] = 0.f;
            #pragma unroll
            for (int k16 = 0; k16 < 2; k16++)
                #pragma unroll
                for (int j = 0; j < 4; j++) {
                    MMA(acc[j], Ah[k16], Bh[k16][j * 2], Bh[k16][j * 2 + 1]);
                    MMA(acc[j], Ah[k16], Bl[k16][j * 2], Bl[k16][j * 2 + 1]);
                    MMA(acc[j], Al[k16], Bh[k16][j * 2], Bh[k16][j * 2 + 1]);
                }
            // epilogue: split u to bf16, scatter into U[r=t*25+w][k=s*64+c]
            #pragma unroll
            for (int j = 0; j < 4; j++)
                #pragma unroll
                for (int half = 0; half < 2; half++) {
                    int grow = wid * 16 + (lane >> 2) + half * 8;
                    int c = grow >> 2, tq = grow & 3;
                    int kcol = s * 64 + c;
                    #pragma unroll
                    for (int e = 0; e < 2; e++) {
                        int w = j * 8 + 2 * (lane & 3) + e;
                        if (w < 25) {
                            int r = tq * 25 + w;
                            unsigned short h, l;
                            bf16split(acc[j][half * 2 + e], h, l);
                            *(unsigned short*)(sm + OFF_UH + r * 400 + kcol * 2) = h;
                            *(unsigned short*)(sm + OFF_UL + r * 400 + kcol * 2) = l;
                        }
                    }
                }
        }
    }
    __syncthreads();

    // ================= Stage 2: z = U * W^T  (M=112, K=192, N=64) =================
    // warps 0..13: mt = wid>>1 (rows mt*16..+15), nh = wid&1 (cols nh*32..+31)
    float zacc[4][4];
    #pragma unroll
    for (int j = 0; j < 4; j++)
        #pragma unroll
        for (int e = 0; e < 4; e++) zacc[j][e] = 0.f;
    const int mt = wid >> 1, nh = wid & 1;
    if (wid < 14) {
        #pragma unroll
        for (int term = 0; term < 3; term++) {
            uint32_t ub = sb + ((term == 2) ? OFF_UL : OFF_UH);
            uint32_t wb = sb + ((term == 1) ? OFF_WL : OFF_WH);
            #pragma unroll 4
            for (int k16 = 0; k16 < 12; k16++) {
                uint32_t A[4], B[8];
                LDSM_X4(A, lm_addr(ub, mt * 16, k16 * 32, 400, lane));
                #pragma unroll
                for (int n16 = 0; n16 < 2; n16++)
                    LDSM_X4T(&B[n16 * 4],
                        lm_addr(wb, k16 * 16, nh * 64 + n16 * 32, 144, lane));
                #pragma unroll
                for (int j = 0; j < 4; j++)
                    MMA(zacc[j], A, B[j * 2], B[j * 2 + 1]);
            }
        }
    }
    __syncthreads();   // U reads done everywhere; safe to overwrite with zs

    // restage z through smem (reuse U area): zs[o][r], stride 112 f32
    float* zs = (float*)(sm + OFF_UH);
    if (wid < 14) {
        #pragma unroll
        for (int j = 0; j < 4; j++)
            #pragma unroll
            for (int half = 0; half < 2; half++) {
                int r = mt * 16 + (lane >> 2) + half * 8;
                if (r < 100) {
                    int o = nh * 32 + j * 8 + 2 * (lane & 3);
                    zs[o * 112 + r]       = zacc[j][half * 2];
                    zs[(o + 1) * 112 + r] = zacc[j][half * 2 + 1];
                }
            }
    }
    __syncthreads();

    // final: BN + relu + residual + relu, coalesced-ish stores along w
    if (tid < 256) {
        int o = tid >> 2, tq = tid & 3;
        float sc = ((const float*)(sm + OFF_SCALE))[o];
        float sh = ((const float*)(sm + OFF_SHIFT))[o];
        const float* zb = (const float*)(sm + OFF_ZB);
        long long ob = (((long long)(n * 64 + o)) * 300 + (t0 + tq)) * 25;
        int xrow = (o * TTILE + tq) * 64;
        #pragma unroll 5
        for (int w = 0; w < 25; w++) {
            float z = zs[o * 112 + tq * 25 + w] + zb[o * 25 + w];
            float zn = fmaxf(fmaf(z, sc, sh), 0.f);
            float res = __bfloat162float(*(__nv_bfloat16*)(sm + OFF_XH + xrow + w * 2))
                      + __bfloat162float(*(__nv_bfloat16*)(sm + OFF_XL + xrow + w * 2));
            out[(ob + w) * 2 + m] = fmaxf(zn + res, 0.f);
        }
    }
}

extern "C" void kernel_launch(void* const* d_in, const int* in_sizes, int n_in,
                              void* d_out, int out_size)
{
    cudaFuncSetAttribute(stgcn_mma, cudaFuncAttributeMaxDynamicSharedMemorySize, SMEM_TOTAL);
    stgcn_mma<<<64 * NTILE, THREADS, SMEM_TOTAL>>>(
        (const float*)d_in[0], (const float*)d_in[1], (const float*)d_in[2],
        (const float*)d_in[3], (const float*)d_in[4], (const float*)d_in[5],
        (const float*)d_in[6], (const float*)d_in[7], (float*)d_out);
}

// round 6
// speedup vs baseline: 1.5196x; 1.5196x over previous
#include <cuda_runtime.h>
#include <cuda_bf16.h>
#include <stdint.h>

#define THREADS 512
#define CTAS 296            // 2 per SM
#define ITEMS 9600          // 64 batch * 150 T-tiles (TTILE=2)

// Precomputed constant images (setup kernel writes, main reads)
__device__ __align__(16) unsigned short gWH[192*72];   // W^T rows k=(s*64+c), cols o, 144B stride
__device__ __align__(16) unsigned short gWL[192*72];
__device__ __align__(16) unsigned short gPAH[96*40];   // rows s*32+v, cols w, 80B stride
__device__ __align__(16) unsigned short gPAL[96*40];
__device__ __align__(16) float gZb[1600];              // zb[o][w]
__device__ __align__(16) float gScale[64], gShift[64];

// smem byte offsets
#define OFF_XH   0          // 128 rows (c*2+t) x 80B
#define OFF_XL   10240
#define OFF_PAH  20480      // 96 x 80
#define OFF_PAL  28160
#define OFF_WH   35840      // 192 x 144
#define OFF_WL   63488
#define OFF_USH  91136      // 64 x 144 (U_s hi); zs reuses this region
#define OFF_USL  100352
#define SMEM_TOTAL 109568

#define LDSM_X4(r, a) \
    asm volatile("ldmatrix.sync.aligned.m8n8.x4.shared.b16 {%0,%1,%2,%3}, [%4];" \
        : "=r"((r)[0]), "=r"((r)[1]), "=r"((r)[2]), "=r"((r)[3]) : "r"(a))
#define LDSM_X4T(r, a) \
    asm volatile("ldmatrix.sync.aligned.m8n8.x4.trans.shared.b16 {%0,%1,%2,%3}, [%4];" \
        : "=r"((r)[0]), "=r"((r)[1]), "=r"((r)[2]), "=r"((r)[3]) : "r"(a))
#define MMA(acc, a, b0, b1) \
    asm volatile("mma.sync.aligned.m16n8k16.row.col.f32.bf16.bf16.f32 " \
        "{%0,%1,%2,%3}, {%4,%5,%6,%7}, {%8,%9}, {%0,%1,%2,%3};" \
        : "+f"((acc)[0]), "+f"((acc)[1]), "+f"((acc)[2]), "+f"((acc)[3]) \
        : "r"((a)[0]), "r"((a)[1]), "r"((a)[2]), "r"((a)[3]), "r"(b0), "r"(b1))

__device__ __forceinline__ uint32_t cvta_smem(const void* p) {
    uint32_t a;
    asm("{ .reg .u64 t; cvta.to.shared.u64 t, %1; cvt.u32.u64 %0, t; }" : "=r"(a) : "l"(p));
    return a;
}
__device__ __forceinline__ void bf16split(float v, unsigned short& h, unsigned short& l) {
    __nv_bfloat16 hb = __float2bfloat16_rn(v);
    __nv_bfloat16 lb = __float2bfloat16_rn(v - __bfloat162float(hb));
    h = __bfloat16_as_ushort(hb);
    l = __bfloat16_as_ushort(lb);
}
__device__ __forceinline__ uint32_t lm_addr(uint32_t base, int row0, int colByte,
                                            int stride, int lane) {
    return base + (uint32_t)((row0 + (lane & 15)) * stride + colByte + (lane >> 4) * 16);
}

// ---------------- setup: build padded bf16-split constant images ----------------
__global__ void setup_kernel(const float* __restrict__ PA, const float* __restrict__ Wc,
                             const float* __restrict__ bc, const float* __restrict__ gamma,
                             const float* __restrict__ beta, const float* __restrict__ mean,
                             const float* __restrict__ var)
{
    const int tid = threadIdx.x;
    for (int i = tid; i < 192*72; i += 512) { gWH[i] = 0; gWL[i] = 0; }
    for (int i = tid; i < 96*40;  i += 512) { gPAH[i] = 0; gPAL[i] = 0; }
    __syncthreads();
    for (int i = tid; i < 192*64; i += 512) {
        int so = i >> 6, c = i & 63, s = so >> 6, o = so & 63;
        unsigned short h, l; bf16split(Wc[i], h, l);
        int k = s*64 + c;
        gWH[k*72 + o] = h; gWL[k*72 + o] = l;
    }
    for (int i = tid; i < 1875; i += 512) {
        int s = i / 625, r = i - s*625, v = r / 25, w = r - v*25;
        unsigned short h, l; bf16split(PA[i], h, l);
        gPAH[(s*32 + v)*40 + w] = h; gPAL[(s*32 + v)*40 + w] = l;
    }
    for (int i = tid; i < 1600; i += 512) {
        int o = i / 25, w = i - o*25;
        float acc = 0.f;
        for (int s = 0; s < 3; s++) {
            float cs = 0.f;
            for (int v = 0; v < 25; v++) cs += PA[s*625 + v*25 + w];
            acc += bc[s*64 + o] * cs;
        }
        gZb[i] = acc;
    }
    if (tid < 64) {
        float sc = gamma[tid] * rsqrtf(var[tid] + 1e-5f);
        gScale[tid] = sc; gShift[tid] = beta[tid] - mean[tid] * sc;
    }
}

// ---------------- main persistent kernel ----------------
__global__ __launch_bounds__(THREADS, 2)
void stgcn_main(const float* __restrict__ x, float* __restrict__ out)
{
    extern __shared__ char sm[];
    const uint32_t sb = cvta_smem(sm);
    const int tid = threadIdx.x, wid = tid >> 5, lane = tid & 31;

    // one-time per-CTA: zero X region (pads), copy PA and W images
    {
        uint4 z = make_uint4(0,0,0,0);
        uint4* xr = (uint4*)(sm + OFF_XH);
        for (int i = tid; i < 1280; i += THREADS) xr[i] = z;                // X h+l 20480B
        const uint4* pah = (const uint4*)gPAH; const uint4* pal = (const uint4*)gPAL;
        uint4* dpah = (uint4*)(sm + OFF_PAH); uint4* dpal = (uint4*)(sm + OFF_PAL);
        for (int i = tid; i < 480; i += THREADS) { dpah[i] = pah[i]; dpal[i] = pal[i]; }
        const uint4* wh = (const uint4*)gWH; const uint4* wl = (const uint4*)gWL;
        uint4* dwh = (uint4*)(sm + OFF_WH); uint4* dwl = (uint4*)(sm + OFF_WL);
        for (int i = tid; i < 1728; i += THREADS) { dwh[i] = wh[i]; dwl[i] = wl[i]; }
    }

    const int mt  = wid & 7, ng  = wid >> 3;   // stage-1 roles (8 mt x 2 ng)
    const int mt2 = wid & 3, ng2 = wid >> 2;   // stage-2 roles (4 mt x 4 ng)
    // hoisted output-role constants
    const int oo = tid >> 1, ot = tid & 1;     // valid when tid < 128
    float o_sc = 0.f, o_sh = 0.f;
    if (tid < 128) { o_sc = gScale[oo]; o_sh = gShift[oo]; }

    for (int item = blockIdx.x; item < ITEMS; item += CTAS) {
        const int b = item & 63, tile = item >> 6;
        const int n = b >> 1, m = b & 1, t0 = tile * 2;

        __syncthreads();   // previous iter's X/zs readers done

        // fill X (rows c*2+t, cols v) + re-zero U_s pad rows 50..63
        for (int i = tid; i < 3200; i += THREADS) {
            int row = i / 25, v = i - row * 25;
            int c = row >> 1, t = row & 1;
            float val = x[(((n*64 + c)*300 + (t0 + t))*25 + v)*2 + m];
            unsigned short h, l; bf16split(val, h, l);
            int off = row * 80 + v * 2;
            *(unsigned short*)(sm + OFF_XH + off) = h;
            *(unsigned short*)(sm + OFF_XL + off) = l;
        }
        {
            uint4 z = make_uint4(0,0,0,0);
            for (int i = tid; i < 252; i += THREADS) {
                if (i < 126) ((uint4*)(sm + OFF_USH + 7200))[i] = z;
                else         ((uint4*)(sm + OFF_USL + 7200))[i - 126] = z;
            }
        }
        __syncthreads();

        // stage-1 A fragments (X), reused across s
        uint32_t Ah[2][4], Al[2][4];
        #pragma unroll
        for (int k16 = 0; k16 < 2; k16++) {
            LDSM_X4(Ah[k16], lm_addr(sb + OFF_XH, mt*16, k16*32, 80, lane));
            LDSM_X4(Al[k16], lm_addr(sb + OFF_XL, mt*16, k16*32, 80, lane));
        }

        float zacc[2][4];
        #pragma unroll
        for (int j = 0; j < 2; j++)
            #pragma unroll
            for (int e = 0; e < 4; e++) zacc[j][e] = 0.f;

        for (int s = 0; s < 3; s++) {
            // ---- stage 1: u_s = X * PA_s  (M=128, K=32, N=32) ----
            uint32_t Bh[2][4], Bl[2][4];
            #pragma unroll
            for (int k16 = 0; k16 < 2; k16++) {
                LDSM_X4T(Bh[k16], lm_addr(sb + OFF_PAH + s*2560, k16*16, ng*32, 80, lane));
                LDSM_X4T(Bl[k16], lm_addr(sb + OFF_PAL + s*2560, k16*16, ng*32, 80, lane));
            }
            float acc[2][4];
            #pragma unroll
            for (int j = 0; j < 2; j++)
                #pragma unroll
                for (int e = 0; e < 4; e++) acc[j][e] = 0.f;
            #pragma unroll
            for (int k16 = 0; k16 < 2; k16++)
                #pragma unroll
                for (int j = 0; j < 2; j++) {
                    MMA(acc[j], Ah[k16], Bh[k16][j*2], Bh[k16][j*2+1]);
                    MMA(acc[j], Ah[k16], Bl[k16][j*2], Bl[k16][j*2+1]);
                    MMA(acc[j], Al[k16], Bh[k16][j*2], Bh[k16][j*2+1]);
                }
            // scatter u_s -> Us[r=t*25+w][c], bf16 split
            #pragma unroll
            for (int j = 0; j < 2; j++)
                #pragma unroll
                for (int half = 0; half < 2; half++) {
                    int grow = mt*16 + (lane >> 2) + half*8;
                    int c = grow >> 1, t = grow & 1;
                    #pragma unroll
                    for (int e = 0; e < 2; e++) {
                        int w = ng*16 + j*8 + 2*(lane & 3) + e;
                        if (w < 25) {
                            int r = t*25 + w;
                            unsigned short h, l;
                            bf16split(acc[j][half*2 + e], h, l);
                            *(unsigned short*)(sm + OFF_USH + r*144 + c*2) = h;
                            *(unsigned short*)(sm + OFF_USL + r*144 + c*2) = l;
                        }
                    }
                }
            __syncthreads();   // Us ready

            // ---- stage 2 accumulate: z += Us * W_s^T  (M=64, K=64, N=64) ----
            #pragma unroll
            for (int k16 = 0; k16 < 4; k16++) {
                uint32_t Auh[4], Aul[4], Bwh[4], Bwl[4];
                LDSM_X4 (Auh, lm_addr(sb + OFF_USH, mt2*16, k16*32, 144, lane));
                LDSM_X4 (Aul, lm_addr(sb + OFF_USL, mt2*16, k16*32, 144, lane));
                LDSM_X4T(Bwh, lm_addr(sb + OFF_WH, s*64 + k16*16, ng2*32, 144, lane));
                LDSM_X4T(Bwl, lm_addr(sb + OFF_WL, s*64 + k16*16, ng2*32, 144, lane));
                #pragma unroll
                for (int j = 0; j < 2; j++) {
                    MMA(zacc[j], Auh, Bwh[j*2], Bwh[j*2+1]);
                    MMA(zacc[j], Auh, Bwl[j*2], Bwl[j*2+1]);
                    MMA(zacc[j], Aul, Bwh[j*2], Bwh[j*2+1]);
                }
            }
            __syncthreads();   // stage-2 reads of Us done (next s may overwrite)
        }

        // restage z -> zs[o][r] (stride 52 f32), reusing Us region
        float* zs = (float*)(sm + OFF_USH);
        #pragma unroll
        for (int j = 0; j < 2; j++)
            #pragma unroll
            for (int half = 0; half < 2; half++) {
                int r = mt2*16 + (lane >> 2) + half*8;
                if (r < 50) {
                    int o = ng2*16 + j*8 + 2*(lane & 3);
                    zs[o*52 + r]     = zacc[j][half*2];
                    zs[(o+1)*52 + r] = zacc[j][half*2 + 1];
                }
            }
        __syncthreads();

        // final: BN + relu + residual + relu + store (128 threads: o x t)
        if (tid < 128) {
            const long long ob = (((long long)(n*64 + oo))*300 + (t0 + ot))*25;
            const int xrow = (oo*2 + ot) * 80;
            #pragma unroll 5
            for (int w = 0; w < 25; w++) {
                float z = zs[oo*52 + ot*25 + w] + gZb[oo*25 + w];
                float zn = fmaxf(fmaf(z, o_sc, o_sh), 0.f);
                float res = __bfloat162float(*(__nv_bfloat16*)(sm + OFF_XH + xrow + w*2))
                          + __bfloat162float(*(__nv_bfloat16*)(sm + OFF_XL + xrow + w*2));
                out[(ob + w)*2 + m] = fmaxf(zn + res, 0.f);
            }
        }
    }
}

extern "C" void kernel_launch(void* const* d_in, const int* in_sizes, int n_in,
                              void* d_out, int out_size)
{
    const float* x     = (const float*)d_in[0];
    const float* PA    = (const float*)d_in[1];
    const float* Wc    = (const float*)d_in[2];
    const float* bc    = (const float*)d_in[3];
    const float* gamma = (const float*)d_in[4];
    const float* beta  = (const float*)d_in[5];
    const float* mean  = (const float*)d_in[6];
    const float* var   = (const float*)d_in[7];

    setup_kernel<<<1, 512>>>(PA, Wc, bc, gamma, beta, mean, var);

    cudaFuncSetAttribute(stgcn_main, cudaFuncAttributeMaxDynamicSharedMemorySize, SMEM_TOTAL);
    stgcn_main<<<CTAS, THREADS, SMEM_TOTAL>>>(x, (float*)d_out);
}

// round 10
// speedup vs baseline: 2.6551x; 1.7472x over previous
#include <cuda_runtime.h>
#include <cuda_fp16.h>
#include <stdint.h>

#define THREADS 512
#define CTAS 296            // 2 per SM
#define ITEMS 9600          // 64 batch * 150 T-tiles (TTILE=2)

// Precomputed constant images (fp16-split, R6-proven layouts)
__device__ __align__(16) __half gPAH[96*40];   // rows s*32+v, cols w, 80B stride
__device__ __align__(16) __half gPAL[96*40];
__device__ __align__(16) __half gWH[192*72];   // rows k=(s*64+c), cols o, 144B stride
__device__ __align__(16) __half gWL[192*72];
__device__ __align__(16) float gZb[1600];
__device__ __align__(16) float gScale[64], gShift[64];

// smem byte offsets
#define OFF_X    0          // X: 128 rows (c*2+t) x 80B fp16; US1 overlays [0,9216)
#define OFF_PAH  10240      // 96 x 80
#define OFF_PAL  17920
#define OFF_WH   25600      // 192 x 144
#define OFF_WL   53248
#define OFF_US0  80896      // 64 x 144
#define OFF_ZS   90112      // 64*52 f32
#define OFF_ZB   103424     // 1600 f32
#define OFF_BN   109824     // 64+64 f32
#define SMEM_TOTAL 110336

#define LDSM_X4(r, a) \
    asm volatile("ldmatrix.sync.aligned.m8n8.x4.shared.b16 {%0,%1,%2,%3}, [%4];" \
        : "=r"((r)[0]), "=r"((r)[1]), "=r"((r)[2]), "=r"((r)[3]) : "r"(a))
#define LDSM_X4T(r, a) \
    asm volatile("ldmatrix.sync.aligned.m8n8.x4.trans.shared.b16 {%0,%1,%2,%3}, [%4];" \
        : "=r"((r)[0]), "=r"((r)[1]), "=r"((r)[2]), "=r"((r)[3]) : "r"(a))
#define MMA(acc, a, b0, b1) \
    asm volatile("mma.sync.aligned.m16n8k16.row.col.f32.f16.f16.f32 " \
        "{%0,%1,%2,%3}, {%4,%5,%6,%7}, {%8,%9}, {%0,%1,%2,%3};" \
        : "+f"((acc)[0]), "+f"((acc)[1]), "+f"((acc)[2]), "+f"((acc)[3]) \
        : "r"((a)[0]), "r"((a)[1]), "r"((a)[2]), "r"((a)[3]), "r"(b0), "r"(b1))

__device__ __forceinline__ uint32_t cvta_smem(const void* p) {
    uint32_t a;
    asm("{ .reg .u64 t; cvta.to.shared.u64 t, %1; cvt.u32.u64 %0, t; }" : "=r"(a) : "l"(p));
    return a;
}
__device__ __forceinline__ void f16split(float v, __half& h, __half& l) {
    h = __float2half_rn(v);
    l = __float2half_rn(v - __half2float(h));
}
// R6-proven ldmatrix addressing (padded stride, no swizzle); base is SHARED-space addr
__device__ __forceinline__ uint32_t lm_addr(uint32_t base, int row0, int colByte,
                                            int stride, int lane) {
    return base + (uint32_t)((row0 + (lane & 15)) * stride + colByte + (lane >> 4) * 16);
}

// ---------------- setup ----------------
__global__ void setup_kernel(const float* __restrict__ PA, const float* __restrict__ Wc,
                             const float* __restrict__ bc, const float* __restrict__ gamma,
                             const float* __restrict__ beta, const float* __restrict__ mean,
                             const float* __restrict__ var)
{
    const int tid = threadIdx.x;
    __half z = __float2half(0.f);
    for (int i = tid; i < 96*40;  i += 512) { gPAH[i] = z; gPAL[i] = z; }
    for (int i = tid; i < 192*72; i += 512) { gWH[i]  = z; gWL[i]  = z; }
    __syncthreads();
    for (int i = tid; i < 1875; i += 512) {       // PA rows s*32+v, cols w
        int s = i / 625, r = i - s*625, v = r / 25, w = r - v*25;
        __half h, l; f16split(PA[i], h, l);
        gPAH[(s*32 + v)*40 + w] = h; gPAL[(s*32 + v)*40 + w] = l;
    }
    for (int i = tid; i < 192*64; i += 512) {     // W rows k=s*64+c, cols o
        int so = i >> 6, c = i & 63, s = so >> 6, o = so & 63;
        __half h, l; f16split(Wc[i], h, l);
        int k = s*64 + c;
        gWH[k*72 + o] = h; gWL[k*72 + o] = l;
    }
    for (int i = tid; i < 1600; i += 512) {
        int o = i / 25, w = i - o*25;
        float acc = 0.f;
        for (int s = 0; s < 3; s++) {
            float cs = 0.f;
            for (int v = 0; v < 25; v++) cs += PA[s*625 + v*25 + w];
            acc += bc[s*64 + o] * cs;
        }
        gZb[i] = acc;
    }
    if (tid < 64) {
        float sc = gamma[tid] * rsqrtf(var[tid] + 1e-5f);
        gScale[tid] = sc; gShift[tid] = beta[tid] - mean[tid] * sc;
    }
}

// ---------------- main persistent kernel ----------------
__global__ __launch_bounds__(THREADS, 2)
void stgcn_main(const float* __restrict__ x, float* __restrict__ out)
{
    extern __shared__ char sm[];
    const uint32_t sb = cvta_smem(sm);
    const int tid = threadIdx.x, wid = tid >> 5, lane = tid & 31;

    // one-time: zero US0 pad rows (50..63), copy constants
    {
        uint4 z4 = make_uint4(0,0,0,0);
        for (int i = tid; i < 126; i += THREADS)
            ((uint4*)(sm + OFF_US0 + 7200))[i] = z4;
        for (int i = tid; i < 480; i += THREADS) {
            ((uint4*)(sm + OFF_PAH))[i] = ((const uint4*)gPAH)[i];
            ((uint4*)(sm + OFF_PAL))[i] = ((const uint4*)gPAL)[i];
        }
        for (int i = tid; i < 1728; i += THREADS) {
            ((uint4*)(sm + OFF_WH))[i] = ((const uint4*)gWH)[i];
            ((uint4*)(sm + OFF_WL))[i] = ((const uint4*)gWL)[i];
        }
        for (int i = tid; i < 400; i += THREADS)
            ((uint4*)(sm + OFF_ZB))[i] = ((const uint4*)gZb)[i];
        if (tid < 64) {
            ((float*)(sm + OFF_BN))[tid]      = gScale[tid];
            ((float*)(sm + OFF_BN))[64 + tid] = gShift[tid];
        }
    }

    const int mt  = wid & 7, ng  = wid >> 3;   // stage-1 roles (8 x 2)
    const int mt2 = wid & 3, ng2 = wid >> 2;   // stage-2 roles (4 x 4)

    // stage1: u_s = X * PA_s (M=128,K=32,N=32), 2-term on PA; scatter fp16 into Us.
    // usOff is a BYTE OFFSET (generic stores use sm+off; ldmatrix uses sb+off).
    auto stage1 = [&](int s, int usOff, const uint32_t Ah[2][4]) {
        uint32_t Bh[2][4], Bl[2][4];
        #pragma unroll
        for (int k16 = 0; k16 < 2; k16++) {
            LDSM_X4T(Bh[k16], lm_addr(sb + OFF_PAH, s*32 + k16*16, ng*32, 80, lane));
            LDSM_X4T(Bl[k16], lm_addr(sb + OFF_PAL, s*32 + k16*16, ng*32, 80, lane));
        }
        float acc[2][4];
        #pragma unroll
        for (int j = 0; j < 2; j++)
            #pragma unroll
            for (int e = 0; e < 4; e++) acc[j][e] = 0.f;
        #pragma unroll
        for (int k16 = 0; k16 < 2; k16++)
            #pragma unroll
            for (int j = 0; j < 2; j++) {
                MMA(acc[j], Ah[k16], Bh[k16][j*2], Bh[k16][j*2+1]);
                MMA(acc[j], Ah[k16], Bl[k16][j*2], Bl[k16][j*2+1]);
            }
        #pragma unroll
        for (int j = 0; j < 2; j++)
            #pragma unroll
            for (int half = 0; half < 2; half++) {
                int grow = mt*16 + (lane >> 2) + half*8;   // X row = c*2+t
                int c = grow >> 1, t = grow & 1;
                #pragma unroll
                for (int e = 0; e < 2; e++) {
                    int w = ng*16 + j*8 + 2*(lane & 3) + e;
                    if (w < 25) {
                        int r2 = t*25 + w;
                        *(__half*)(sm + usOff + r2*144 + c*2) =
                            __float2half_rn(acc[j][half*2 + e]);
                    }
                }
            }
    };
    // stage2: zacc += Us * W_s^T (M=64,K=64,N=64), 2-term on W
    auto stage2 = [&](int s, int usOff, float zacc[2][4]) {
        #pragma unroll
        for (int k16 = 0; k16 < 4; k16++) {
            uint32_t Au[4], Bwh[4], Bwl[4];
            LDSM_X4 (Au,  lm_addr(sb + usOff, mt2*16, k16*32, 144, lane));
            LDSM_X4T(Bwh, lm_addr(sb + OFF_WH, s*64 + k16*16, ng2*32, 144, lane));
            LDSM_X4T(Bwl, lm_addr(sb + OFF_WL, s*64 + k16*16, ng2*32, 144, lane));
            #pragma unroll
            for (int j = 0; j < 2; j++) {
                MMA(zacc[j], Au, Bwh[j*2], Bwh[j*2+1]);
                MMA(zacc[j], Au, Bwl[j*2], Bwl[j*2+1]);
            }
        }
    };

    for (int item = blockIdx.x; item < ITEMS; item += CTAS) {
        const int b = item & 63, tile = item >> 6;
        const int n = b >> 1, m = b & 1, t0 = tile * 2;

        __syncthreads();                       // barTop: prev item fully consumed

        // fill X fp16 (rows c*2+t, 32 v-slots; v>=25 -> 0, re-clearing US1 dirt)
        for (int i = tid; i < 4096; i += THREADS) {
            int row = i >> 5, v = i & 31;
            int c = row >> 1, t = row & 1;
            __half hv = __float2half(0.f);
            if (v < 25)
                hv = __float2half_rn(x[(((n*64 + c)*300 + (t0 + t))*25 + v)*2 + m]);
            *(__half*)(sm + OFF_X + row*80 + v*2) = hv;
        }
        __syncthreads();                       // barB: X ready

        uint32_t Ah[2][4];
        #pragma unroll
        for (int k16 = 0; k16 < 2; k16++)
            LDSM_X4(Ah[k16], lm_addr(sb + OFF_X, mt*16, k16*32, 80, lane));
        __syncthreads();                       // barB2: X consumed, region reusable

        // zero US1 pad rows (50..63) dirtied by X fill; run stage1(0)->US0
        {
            uint4 z4 = make_uint4(0,0,0,0);
            for (int i = tid; i < 126; i += THREADS)
                ((uint4*)(sm + OFF_X + 7200))[i] = z4;
        }
        stage1(0, OFF_US0, Ah);

        float zacc[2][4];
        #pragma unroll
        for (int j = 0; j < 2; j++)
            #pragma unroll
            for (int e = 0; e < 4; e++) zacc[j][e] = 0.f;

        __syncthreads();                       // barC: US0 ready, US1 pads zero
        stage1(1, OFF_X, Ah);                  // US1 in X region
        stage2(0, OFF_US0, zacc);
        __syncthreads();                       // barD: US1 ready, US0 reads done
        stage1(2, OFF_US0, Ah);
        stage2(1, OFF_X, zacc);
        __syncthreads();                       // barE: US0(2) ready, US1 reads done
        stage2(2, OFF_US0, zacc);

        // restage z -> zs[o][r] (stride 52 f32), dedicated region
        float* zs = (float*)(sm + OFF_ZS);
        #pragma unroll
        for (int j = 0; j < 2; j++)
            #pragma unroll
            for (int half = 0; half < 2; half++) {
                int r = mt2*16 + (lane >> 2) + half*8;
                if (r < 50) {
                    int o = ng2*16 + j*8 + 2*(lane & 3);
                    zs[o*52 + r]     = zacc[j][half*2];
                    zs[(o+1)*52 + r] = zacc[j][half*2 + 1];
                }
            }
        __syncthreads();                       // barF: zs ready

        // out: BN + relu + residual(global, exact) + relu + store
        const float* zbS = (const float*)(sm + OFF_ZB);
        const float* scS = (const float*)(sm + OFF_BN);
        const float* shS = scS + 64;
        for (int i = tid; i < 3200; i += THREADS) {
            int o = i / 50, rem = i - o*50;
            int t = rem / 25, w = rem - t*25;
            float z = zs[o*52 + t*25 + w] + zbS[o*25 + w];
            float zn = fmaxf(fmaf(z, scS[o], shS[o]), 0.f);
            long long gi = (((long long)(n*64 + o)*300 + (t0 + t))*25 + w)*2 + m;
            out[gi] = fmaxf(zn + x[gi], 0.f);
        }
    }
}

extern "C" void kernel_launch(void* const* d_in, const int* in_sizes, int n_in,
                              void* d_out, int out_size)
{
    const float* x     = (const float*)d_in[0];
    const float* PA    = (const float*)d_in[1];
    const float* Wc    = (const float*)d_in[2];
    const float* bc    = (const float*)d_in[3];
    const float* gamma = (const float*)d_in[4];
    const float* beta  = (const float*)d_in[5];
    const float* mean  = (const float*)d_in[6];
    const float* var   = (const float*)d_in[7];

    setup_kernel<<<1, 512>>>(PA, Wc, bc, gamma, beta, mean, var);

    cudaFuncSetAttribute(stgcn_main, cudaFuncAttributeMaxDynamicSharedMemorySize, SMEM_TOTAL);
    stgcn_main<<<CTAS, THREADS, SMEM_TOTAL>>>(x, (float*)d_out);
}

// round 11
// speedup vs baseline: 3.5939x; 1.3536x over previous
#include <cuda_runtime.h>
#include <cuda_fp16.h>
#include <stdint.h>

#define THREADS 512
#define CTAS 296            // 2 per SM
#define ITEMS 9600          // 64 batch * 150 T-tiles (TTILE=2)

// Precomputed constant images (plain fp16, R6-proven layouts)
__device__ __align__(16) __half gPA[96*40];    // rows s*32+v, cols w, 80B stride
__device__ __align__(16) __half gW[192*72];    // rows k=(s*64+c), cols o, 144B stride
__device__ __align__(16) float gZb[1600];
__device__ __align__(16) float gScale[64], gShift[64];

// smem byte offsets
#define OFF_X    0          // X: 128 rows (c*2+t) x 80B fp16
#define OFF_PA   10240      // 96 x 80
#define OFF_W    17920      // 192 x 144
#define OFF_US0  45568      // 64 x 144
#define OFF_US1  54784      // 64 x 144
#define OFF_ZS   64000      // 64*52 f32
#define OFF_ZB   77312      // 1600 f32
#define OFF_BN   83712      // 64+64 f32
#define SMEM_TOTAL 84224

#define LDSM_X4(r, a) \
    asm volatile("ldmatrix.sync.aligned.m8n8.x4.shared.b16 {%0,%1,%2,%3}, [%4];" \
        : "=r"((r)[0]), "=r"((r)[1]), "=r"((r)[2]), "=r"((r)[3]) : "r"(a))
#define LDSM_X4T(r, a) \
    asm volatile("ldmatrix.sync.aligned.m8n8.x4.trans.shared.b16 {%0,%1,%2,%3}, [%4];" \
        : "=r"((r)[0]), "=r"((r)[1]), "=r"((r)[2]), "=r"((r)[3]) : "r"(a))
#define MMA(acc, a, b0, b1) \
    asm volatile("mma.sync.aligned.m16n8k16.row.col.f32.f16.f16.f32 " \
        "{%0,%1,%2,%3}, {%4,%5,%6,%7}, {%8,%9}, {%0,%1,%2,%3};" \
        : "+f"((acc)[0]), "+f"((acc)[1]), "+f"((acc)[2]), "+f"((acc)[3]) \
        : "r"((a)[0]), "r"((a)[1]), "r"((a)[2]), "r"((a)[3]), "r"(b0), "r"(b1))

__device__ __forceinline__ uint32_t cvta_smem(const void* p) {
    uint32_t a;
    asm("{ .reg .u64 t; cvta.to.shared.u64 t, %1; cvt.u32.u64 %0, t; }" : "=r"(a) : "l"(p));
    return a;
}
// R6-proven ldmatrix addressing (padded stride, no swizzle); base is SHARED-space addr
__device__ __forceinline__ uint32_t lm_addr(uint32_t base, int row0, int colByte,
                                            int stride, int lane) {
    return base + (uint32_t)((row0 + (lane & 15)) * stride + colByte + (lane >> 4) * 16);
}

// ---------------- setup ----------------
__global__ void setup_kernel(const float* __restrict__ PA, const float* __restrict__ Wc,
                             const float* __restrict__ bc, const float* __restrict__ gamma,
                             const float* __restrict__ beta, const float* __restrict__ mean,
                             const float* __restrict__ var)
{
    const int tid = threadIdx.x;
    __half z = __float2half(0.f);
    for (int i = tid; i < 96*40;  i += 512) gPA[i] = z;
    for (int i = tid; i < 192*72; i += 512) gW[i]  = z;
    __syncthreads();
    for (int i = tid; i < 1875; i += 512) {       // PA rows s*32+v, cols w
        int s = i / 625, r = i - s*625, v = r / 25, w = r - v*25;
        gPA[(s*32 + v)*40 + w] = __float2half_rn(PA[i]);
    }
    for (int i = tid; i < 192*64; i += 512) {     // W rows k=s*64+c, cols o
        int so = i >> 6, c = i & 63, s = so >> 6, o = so & 63;
        gW[(s*64 + c)*72 + o] = __float2half_rn(Wc[i]);
    }
    for (int i = tid; i < 1600; i += 512) {
        int o = i / 25, w = i - o*25;
        float acc = 0.f;
        for (int s = 0; s < 3; s++) {
            float cs = 0.f;
            for (int v = 0; v < 25; v++) cs += PA[s*625 + v*25 + w];
            acc += bc[s*64 + o] * cs;
        }
        gZb[i] = acc;
    }
    if (tid < 64) {
        float sc = gamma[tid] * rsqrtf(var[tid] + 1e-5f);
        gScale[tid] = sc; gShift[tid] = beta[tid] - mean[tid] * sc;
    }
}

// ---------------- main persistent kernel ----------------
__global__ __launch_bounds__(THREADS, 2)
void stgcn_main(const float* __restrict__ x, float* __restrict__ out)
{
    extern __shared__ char sm[];
    const uint32_t sb = cvta_smem(sm);
    const int tid = threadIdx.x, wid = tid >> 5, lane = tid & 31;

    // one-time: zero US pad rows (50..63 of both buffers), copy constants
    {
        uint4 z4 = make_uint4(0,0,0,0);
        for (int i = tid; i < 126; i += THREADS) {
            ((uint4*)(sm + OFF_US0 + 7200))[i] = z4;
            ((uint4*)(sm + OFF_US1 + 7200))[i] = z4;
        }
        for (int i = tid; i < 480; i += THREADS)
            ((uint4*)(sm + OFF_PA))[i] = ((const uint4*)gPA)[i];
        for (int i = tid; i < 1728; i += THREADS)
            ((uint4*)(sm + OFF_W))[i] = ((const uint4*)gW)[i];
        for (int i = tid; i < 400; i += THREADS)
            ((uint4*)(sm + OFF_ZB))[i] = ((const uint4*)gZb)[i];
        if (tid < 64) {
            ((float*)(sm + OFF_BN))[tid]      = gScale[tid];
            ((float*)(sm + OFF_BN))[64 + tid] = gShift[tid];
        }
    }

    const int mt  = wid & 7, ng  = wid >> 3;   // stage-1 roles (8 x 2)
    const int mt2 = wid & 3, ng2 = wid >> 2;   // stage-2 roles (4 x 4)

    // X-fill per-thread invariants: row0 = tid>>5 (0..15), v = tid&31
    const int frow0 = tid >> 5, fv = tid & 31;
    const int ft = frow0 & 1, fc0 = frow0 >> 1;
    const int fvalid = (fv < 25);
    const int fvc = fvalid ? fv : 24;                  // clamp keeps LDG in-bounds
    const int fsoff = OFF_X + frow0*80 + fv*2;         // += 1280 per k (row += 16)

    // stage1: u_s = X * PA_s (M=128,K=32,N=32), single-term; scatter fp16 into Us
    auto stage1 = [&](int s, int usOff, const uint32_t Ah[2][4]) {
        uint32_t Bh[2][4];
        #pragma unroll
        for (int k16 = 0; k16 < 2; k16++)
            LDSM_X4T(Bh[k16], lm_addr(sb + OFF_PA, s*32 + k16*16, ng*32, 80, lane));
        float acc[2][4];
        #pragma unroll
        for (int j = 0; j < 2; j++)
            #pragma unroll
            for (int e = 0; e < 4; e++) acc[j][e] = 0.f;
        #pragma unroll
        for (int k16 = 0; k16 < 2; k16++)
            #pragma unroll
            for (int j = 0; j < 2; j++)
                MMA(acc[j], Ah[k16], Bh[k16][j*2], Bh[k16][j*2+1]);
        #pragma unroll
        for (int j = 0; j < 2; j++)
            #pragma unroll
            for (int half = 0; half < 2; half++) {
                int grow = mt*16 + (lane >> 2) + half*8;   // X row = c*2+t
                int c = grow >> 1, t = grow & 1;
                #pragma unroll
                for (int e = 0; e < 2; e++) {
                    int w = ng*16 + j*8 + 2*(lane & 3) + e;
                    if (w < 25) {
                        int r2 = t*25 + w;
                        *(__half*)(sm + usOff + r2*144 + c*2) =
                            __float2half_rn(acc[j][half*2 + e]);
                    }
                }
            }
    };
    // stage2: zacc += Us * W_s^T (M=64,K=64,N=64), single-term
    auto stage2 = [&](int s, int usOff, float zacc[2][4]) {
        #pragma unroll
        for (int k16 = 0; k16 < 4; k16++) {
            uint32_t Au[4], Bw[4];
            LDSM_X4 (Au, lm_addr(sb + usOff, mt2*16, k16*32, 144, lane));
            LDSM_X4T(Bw, lm_addr(sb + OFF_W, s*64 + k16*16, ng2*32, 144, lane));
            #pragma unroll
            for (int j = 0; j < 2; j++)
                MMA(zacc[j], Au, Bw[j*2], Bw[j*2+1]);
        }
    };

    for (int item = blockIdx.x; item < ITEMS; item += CTAS) {
        const int b = item & 63, tile = item >> 6;
        const int n = b >> 1, m = b & 1, t0 = tile * 2;

        __syncthreads();                       // barTop: prev item fully consumed

        // fill X fp16 — hoisted addressing, 8 x (LDG, CVT, STS)
        {
            long long gbase = (((long long)(n*64 + fc0)*300 + (t0 + ft))*25 + fvc)*2 + m;
            #pragma unroll
            for (int k = 0; k < 8; k++) {
                float xv = x[gbase + (long long)k*120000];
                __half hv = fvalid ? __float2half_rn(xv) : __float2half(0.f);
                *(__half*)(sm + fsoff + k*1280) = hv;
            }
        }
        __syncthreads();                       // barB: X ready

        uint32_t Ah[2][4];
        #pragma unroll
        for (int k16 = 0; k16 < 2; k16++)
            LDSM_X4(Ah[k16], lm_addr(sb + OFF_X, mt*16, k16*32, 80, lane));

        float zacc[2][4];
        #pragma unroll
        for (int j = 0; j < 2; j++)
            #pragma unroll
            for (int e = 0; e < 4; e++) zacc[j][e] = 0.f;

        stage1(0, OFF_US0, Ah);
        __syncthreads();                       // barC: US0 ready
        stage1(1, OFF_US1, Ah);
        stage2(0, OFF_US0, zacc);
        __syncthreads();                       // barD: US1 ready, US0 reads done
        stage1(2, OFF_US0, Ah);
        stage2(1, OFF_US1, zacc);
        __syncthreads();                       // barE: US0(2) ready, US1 reads done
        stage2(2, OFF_US0, zacc);

        // restage z -> zs[o][r] (stride 52 f32)
        float* zs = (float*)(sm + OFF_ZS);
        #pragma unroll
        for (int j = 0; j < 2; j++)
            #pragma unroll
            for (int half = 0; half < 2; half++) {
                int r = mt2*16 + (lane >> 2) + half*8;
                if (r < 50) {
                    int o = ng2*16 + j*8 + 2*(lane & 3);
                    zs[o*52 + r]     = zacc[j][half*2];
                    zs[(o+1)*52 + r] = zacc[j][half*2 + 1];
                }
            }
        __syncthreads();                       // barF: zs ready

        // out: BN + relu + residual(global, exact) + relu + store
        const float* zbS = (const float*)(sm + OFF_ZB);
        const float* scS = (const float*)(sm + OFF_BN);
        const float* shS = scS + 64;
        for (int i = tid; i < 3200; i += THREADS) {
            int o = i / 50, rem = i - o*50;
            int t = rem / 25, w = rem - t*25;
            float z = zs[o*52 + t*25 + w] + zbS[o*25 + w];
            float zn = fmaxf(fmaf(z, scS[o], shS[o]), 0.f);
            long long gi = (((long long)(n*64 + o)*300 + (t0 + t))*25 + w)*2 + m;
            out[gi] = fmaxf(zn + x[gi], 0.f);
        }
    }
}

extern "C" void kernel_launch(void* const* d_in, const int* in_sizes, int n_in,
                              void* d_out, int out_size)
{
    const float* x     = (const float*)d_in[0];
    const float* PA    = (const float*)d_in[1];
    const float* Wc    = (const float*)d_in[2];
    const float* bc    = (const float*)d_in[3];
    const float* gamma = (const float*)d_in[4];
    const float* beta  = (const float*)d_in[5];
    const float* mean  = (const float*)d_in[6];
    const float* var   = (const float*)d_in[7];

    setup_kernel<<<1, 512>>>(PA, Wc, bc, gamma, beta, mean, var);

    cudaFuncSetAttribute(stgcn_main, cudaFuncAttributeMaxDynamicSharedMemorySize, SMEM_TOTAL);
    stgcn_main<<<CTAS, THREADS, SMEM_TOTAL>>>(x, (float*)d_out);
}

// round 12
// speedup vs baseline: 4.1075x; 1.1429x over previous
#include <cuda_runtime.h>
#include <cuda_fp16.h>
#include <stdint.h>

#define THREADS 512
#define CTAS 296            // 2 per SM
#define ITEMS 9600          // 64 batch * 150 T-tiles (TTILE=2)

// Precomputed constant images (plain fp16, R6-proven layouts)
__device__ __align__(16) __half gPA[96*40];    // rows s*32+v, cols w, 80B stride
__device__ __align__(16) __half gW[192*72];    // rows k=(s*64+c), cols o, 144B stride
__device__ __align__(16) float gZb[1600];
__device__ __align__(16) float gScale[64], gShift[64];

// smem byte offsets
#define OFF_X    0          // X: 128 rows (c*2+t) x 80B fp16
#define OFF_PA   10240      // 96 x 80
#define OFF_W    17920      // 192 x 144
#define OFF_US0  45568      // 64 x 144
#define OFF_US1  54784      // 64 x 144
#define OFF_ZB   64000      // 1600 f32
#define OFF_BN   70400      // 64+64 f32
#define SMEM_TOTAL 70912

#define LDSM_X4(r, a) \
    asm volatile("ldmatrix.sync.aligned.m8n8.x4.shared.b16 {%0,%1,%2,%3}, [%4];" \
        : "=r"((r)[0]), "=r"((r)[1]), "=r"((r)[2]), "=r"((r)[3]) : "r"(a))
#define LDSM_X4T(r, a) \
    asm volatile("ldmatrix.sync.aligned.m8n8.x4.trans.shared.b16 {%0,%1,%2,%3}, [%4];" \
        : "=r"((r)[0]), "=r"((r)[1]), "=r"((r)[2]), "=r"((r)[3]) : "r"(a))
#define MMA(acc, a, b0, b1) \
    asm volatile("mma.sync.aligned.m16n8k16.row.col.f32.f16.f16.f32 " \
        "{%0,%1,%2,%3}, {%4,%5,%6,%7}, {%8,%9}, {%0,%1,%2,%3};" \
        : "+f"((acc)[0]), "+f"((acc)[1]), "+f"((acc)[2]), "+f"((acc)[3]) \
        : "r"((a)[0]), "r"((a)[1]), "r"((a)[2]), "r"((a)[3]), "r"(b0), "r"(b1))

__device__ __forceinline__ uint32_t cvta_smem(const void* p) {
    uint32_t a;
    asm("{ .reg .u64 t; cvta.to.shared.u64 t, %1; cvt.u32.u64 %0, t; }" : "=r"(a) : "l"(p));
    return a;
}
// R6-proven ldmatrix addressing (padded stride, no swizzle); base is SHARED-space addr
__device__ __forceinline__ uint32_t lm_addr(uint32_t base, int row0, int colByte,
                                            int stride, int lane) {
    return base + (uint32_t)((row0 + (lane & 15)) * stride + colByte + (lane >> 4) * 16);
}

// ---------------- setup ----------------
__global__ void setup_kernel(const float* __restrict__ PA, const float* __restrict__ Wc,
                             const float* __restrict__ bc, const float* __restrict__ gamma,
                             const float* __restrict__ beta, const float* __restrict__ mean,
                             const float* __restrict__ var)
{
    const int tid = threadIdx.x;
    __half z = __float2half(0.f);
    for (int i = tid; i < 96*40;  i += 512) gPA[i] = z;
    for (int i = tid; i < 192*72; i += 512) gW[i]  = z;
    __syncthreads();
    for (int i = tid; i < 1875; i += 512) {       // PA rows s*32+v, cols w
        int s = i / 625, r = i - s*625, v = r / 25, w = r - v*25;
        gPA[(s*32 + v)*40 + w] = __float2half_rn(PA[i]);
    }
    for (int i = tid; i < 192*64; i += 512) {     // W rows k=s*64+c, cols o
        int so = i >> 6, c = i & 63, s = so >> 6, o = so & 63;
        gW[(s*64 + c)*72 + o] = __float2half_rn(Wc[i]);
    }
    for (int i = tid; i < 1600; i += 512) {
        int o = i / 25, w = i - o*25;
        float acc = 0.f;
        for (int s = 0; s < 3; s++) {
            float cs = 0.f;
            for (int v = 0; v < 25; v++) cs += PA[s*625 + v*25 + w];
            acc += bc[s*64 + o] * cs;
        }
        gZb[i] = acc;
    }
    if (tid < 64) {
        float sc = gamma[tid] * rsqrtf(var[tid] + 1e-5f);
        gScale[tid] = sc; gShift[tid] = beta[tid] - mean[tid] * sc;
    }
}

// ---------------- main persistent kernel ----------------
__global__ __launch_bounds__(THREADS, 2)
void stgcn_main(const float* __restrict__ x, float* __restrict__ out)
{
    extern __shared__ char sm[];
    const uint32_t sb = cvta_smem(sm);
    const int tid = threadIdx.x, wid = tid >> 5, lane = tid & 31;

    // one-time: zero US pad rows (50..63 of both buffers), copy constants
    {
        uint4 z4 = make_uint4(0,0,0,0);
        for (int i = tid; i < 126; i += THREADS) {
            ((uint4*)(sm + OFF_US0 + 7200))[i] = z4;
            ((uint4*)(sm + OFF_US1 + 7200))[i] = z4;
        }
        for (int i = tid; i < 480; i += THREADS)
            ((uint4*)(sm + OFF_PA))[i] = ((const uint4*)gPA)[i];
        for (int i = tid; i < 1728; i += THREADS)
            ((uint4*)(sm + OFF_W))[i] = ((const uint4*)gW)[i];
        for (int i = tid; i < 400; i += THREADS)
            ((uint4*)(sm + OFF_ZB))[i] = ((const uint4*)gZb)[i];
        if (tid < 64) {
            ((float*)(sm + OFF_BN))[tid]      = gScale[tid];
            ((float*)(sm + OFF_BN))[64 + tid] = gShift[tid];
        }
    }

    const int mt  = wid & 7, ng  = wid >> 3;   // stage-1 roles (8 x 2)
    const int mt2 = wid & 3, ng2 = wid >> 2;   // stage-2 roles (4 x 4)

    // X-fill per-thread invariants: row0 = tid>>5 (0..15), v = tid&31
    const int frow0 = tid >> 5, fv = tid & 31;
    const int ft = frow0 & 1, fc0 = frow0 >> 1;
    const int fvalid = (fv < 25);
    const int fvc = fvalid ? fv : 24;                  // clamp keeps LDG in-bounds
    const int fsoff = OFF_X + frow0*80 + fv*2;         // += 1280 per k (row += 16)

    // epilogue per-thread invariants (stage-2 fragment mapping)
    const int erb = mt2*16 + (lane >> 2);
    const int eob = ng2*16 + 2*(lane & 3);

    // stage1: u_s = X * PA_s (M=128,K=32,N=32), single-term; scatter fp16 into Us
    auto stage1 = [&](int s, int usOff, const uint32_t Ah[2][4]) {
        uint32_t Bh[2][4];
        #pragma unroll
        for (int k16 = 0; k16 < 2; k16++)
            LDSM_X4T(Bh[k16], lm_addr(sb + OFF_PA, s*32 + k16*16, ng*32, 80, lane));
        float acc[2][4];
        #pragma unroll
        for (int j = 0; j < 2; j++)
            #pragma unroll
            for (int e = 0; e < 4; e++) acc[j][e] = 0.f;
        #pragma unroll
        for (int k16 = 0; k16 < 2; k16++)
            #pragma unroll
            for (int j = 0; j < 2; j++)
                MMA(acc[j], Ah[k16], Bh[k16][j*2], Bh[k16][j*2+1]);
        #pragma unroll
        for (int j = 0; j < 2; j++)
            #pragma unroll
            for (int half = 0; half < 2; half++) {
                int grow = mt*16 + (lane >> 2) + half*8;   // X row = c*2+t
                int c = grow >> 1, t = grow & 1;
                #pragma unroll
                for (int e = 0; e < 2; e++) {
                    int w = ng*16 + j*8 + 2*(lane & 3) + e;
                    if (w < 25) {
                        int r2 = t*25 + w;
                        *(__half*)(sm + usOff + r2*144 + c*2) =
                            __float2half_rn(acc[j][half*2 + e]);
                    }
                }
            }
    };
    // stage2: zacc += Us * W_s^T (M=64,K=64,N=64), single-term
    auto stage2 = [&](int s, int usOff, float zacc[2][4]) {
        #pragma unroll
        for (int k16 = 0; k16 < 4; k16++) {
            uint32_t Au[4], Bw[4];
            LDSM_X4 (Au, lm_addr(sb + usOff, mt2*16, k16*32, 144, lane));
            LDSM_X4T(Bw, lm_addr(sb + OFF_W, s*64 + k16*16, ng2*32, 144, lane));
            #pragma unroll
            for (int j = 0; j < 2; j++)
                MMA(zacc[j], Au, Bw[j*2], Bw[j*2+1]);
        }
    };

    for (int item = blockIdx.x; item < ITEMS; item += CTAS) {
        const int b = item & 63, tile = item >> 6;
        const int n = b >> 1, m = b & 1, t0 = tile * 2;

        // fill X fp16 — hoisted addressing, 8 x (LDG, CVT, STS).
        // No barrier needed before: X was last read before this item's
        // predecessor's barC; epilogue touches no mutable smem.
        {
            long long gbase = (((long long)(n*64 + fc0)*300 + (t0 + ft))*25 + fvc)*2 + m;
            #pragma unroll
            for (int k = 0; k < 8; k++) {
                float xv = x[gbase + (long long)k*120000];
                __half hv = fvalid ? __float2half_rn(xv) : __float2half(0.f);
                *(__half*)(sm + fsoff + k*1280) = hv;
            }
        }
        __syncthreads();                       // barB: X ready; prev US0 reads done

        uint32_t Ah[2][4];
        #pragma unroll
        for (int k16 = 0; k16 < 2; k16++)
            LDSM_X4(Ah[k16], lm_addr(sb + OFF_X, mt*16, k16*32, 80, lane));

        float zacc[2][4];
        #pragma unroll
        for (int j = 0; j < 2; j++)
            #pragma unroll
            for (int e = 0; e < 4; e++) zacc[j][e] = 0.f;

        stage1(0, OFF_US0, Ah);
        __syncthreads();                       // barC: US0 ready
        stage1(1, OFF_US1, Ah);
        stage2(0, OFF_US0, zacc);
        __syncthreads();                       // barD: US1 ready, US0 reads done
        stage1(2, OFF_US0, Ah);
        stage2(1, OFF_US1, zacc);
        __syncthreads();                       // barE: US0(2) ready, US1 reads done
        stage2(2, OFF_US0, zacc);

        // epilogue: direct from fragments — BN + relu + residual + relu + store
        {
            const float* zbS = (const float*)(sm + OFF_ZB);
            const float* scS = (const float*)(sm + OFF_BN);
            const float* shS = scS + 64;
            const long long gb = (long long)n*960000 + t0*50 + m;
            #pragma unroll
            for (int half = 0; half < 2; half++) {
                int r = erb + half*8;
                if (r < 50) {
                    int t = (r >= 25) ? 1 : 0;
                    int w = r - t*25;
                    long long gtw = gb + t*50 + w*2;
                    #pragma unroll
                    for (int j = 0; j < 2; j++)
                        #pragma unroll
                        for (int e = 0; e < 2; e++) {
                            int o = eob + j*8 + e;
                            float z = zacc[j][half*2 + e] + zbS[o*25 + w];
                            float zn = fmaxf(fmaf(z, scS[o], shS[o]), 0.f);
                            long long gi = gtw + o*15000;
                            out[gi] = fmaxf(zn + x[gi], 0.f);
                        }
                }
            }
        }
    }
}

extern "C" void kernel_launch(void* const* d_in, const int* in_sizes, int n_in,
                              void* d_out, int out_size)
{
    const float* x     = (const float*)d_in[0];
    const float* PA    = (const float*)d_in[1];
    const float* Wc    = (const float*)d_in[2];
    const float* bc    = (const float*)d_in[3];
    const float* gamma = (const float*)d_in[4];
    const float* beta  = (const float*)d_in[5];
    const float* mean  = (const float*)d_in[6];
    const float* var   = (const float*)d_in[7];

    setup_kernel<<<1, 512>>>(PA, Wc, bc, gamma, beta, mean, var);

    cudaFuncSetAttribute(stgcn_main, cudaFuncAttributeMaxDynamicSharedMemorySize, SMEM_TOTAL);
    stgcn_main<<<CTAS, THREADS, SMEM_TOTAL>>>(x, (float*)d_out);
}

// round 13
// speedup vs baseline: 4.1387x; 1.0076x over previous
#include <cuda_runtime.h>
#include <cuda_fp16.h>
#include <stdint.h>

#define THREADS 512
#define CTAS 296            // 2 per SM
#define ITEMS 9600          // 64 batch * 150 T-tiles (TTILE=2)

// Precomputed constant images (plain fp16, R6-proven layouts)
__device__ __align__(16) __half gPA[96*40];    // rows s*32+v, cols w, 80B stride
__device__ __align__(16) __half gW[192*72];    // rows k=(s*64+c), cols o, 144B stride
__device__ __align__(16) float gZb[1600];
__device__ __align__(16) float gScale[64], gShift[64];

// smem byte offsets
#define OFF_X    0          // X: 128 rows (c*2+t) x 80B fp16
#define OFF_PA   10240      // 96 x 80
#define OFF_W    17920      // 192 x 144
#define OFF_US0  45568      // U transposed: 64 rows (c) x 144B (72 el, cols r'=t*32+w)
#define OFF_US1  54784
#define OFF_ZB   64000      // 1600 f32
#define OFF_BN   70400      // 64+64 f32
#define SMEM_TOTAL 70912

#define LDSM_X4(r, a) \
    asm volatile("ldmatrix.sync.aligned.m8n8.x4.shared.b16 {%0,%1,%2,%3}, [%4];" \
        : "=r"((r)[0]), "=r"((r)[1]), "=r"((r)[2]), "=r"((r)[3]) : "r"(a))
#define LDSM_X4T(r, a) \
    asm volatile("ldmatrix.sync.aligned.m8n8.x4.trans.shared.b16 {%0,%1,%2,%3}, [%4];" \
        : "=r"((r)[0]), "=r"((r)[1]), "=r"((r)[2]), "=r"((r)[3]) : "r"(a))
#define MMA(acc, a0, a1, a2, a3, b0, b1) \
    asm volatile("mma.sync.aligned.m16n8k16.row.col.f32.f16.f16.f32 " \
        "{%0,%1,%2,%3}, {%4,%5,%6,%7}, {%8,%9}, {%0,%1,%2,%3};" \
        : "+f"((acc)[0]), "+f"((acc)[1]), "+f"((acc)[2]), "+f"((acc)[3]) \
        : "r"(a0), "r"(a1), "r"(a2), "r"(a3), "r"(b0), "r"(b1))

__device__ __forceinline__ uint32_t cvta_smem(const void* p) {
    uint32_t a;
    asm("{ .reg .u64 t; cvta.to.shared.u64 t, %1; cvt.u32.u64 %0, t; }" : "=r"(a) : "l"(p));
    return a;
}
// R6-proven ldmatrix addressing (padded stride, no swizzle); base is SHARED-space addr
__device__ __forceinline__ uint32_t lm_addr(uint32_t base, int row0, int colByte,
                                            int stride, int lane) {
    return base + (uint32_t)((row0 + (lane & 15)) * stride + colByte + (lane >> 4) * 16);
}

// ---------------- setup ----------------
__global__ void setup_kernel(const float* __restrict__ PA, const float* __restrict__ Wc,
                             const float* __restrict__ bc, const float* __restrict__ gamma,
                             const float* __restrict__ beta, const float* __restrict__ mean,
                             const float* __restrict__ var)
{
    const int tid = threadIdx.x;
    __half z = __float2half(0.f);
    for (int i = tid; i < 96*40;  i += 512) gPA[i] = z;
    for (int i = tid; i < 192*72; i += 512) gW[i]  = z;
    __syncthreads();
    for (int i = tid; i < 1875; i += 512) {       // PA rows s*32+v, cols w
        int s = i / 625, r = i - s*625, v = r / 25, w = r - v*25;
        gPA[(s*32 + v)*40 + w] = __float2half_rn(PA[i]);
    }
    for (int i = tid; i < 192*64; i += 512) {     // W rows k=s*64+c, cols o
        int so = i >> 6, c = i & 63, s = so >> 6, o = so & 63;
        gW[(s*64 + c)*72 + o] = __float2half_rn(Wc[i]);
    }
    for (int i = tid; i < 1600; i += 512) {
        int o = i / 25, w = i - o*25;
        float acc = 0.f;
        for (int s = 0; s < 3; s++) {
            float cs = 0.f;
            for (int v = 0; v < 25; v++) cs += PA[s*625 + v*25 + w];
            acc += bc[s*64 + o] * cs;
        }
        gZb[i] = acc;
    }
    if (tid < 64) {
        float sc = gamma[tid] * rsqrtf(var[tid] + 1e-5f);
        gScale[tid] = sc; gShift[tid] = beta[tid] - mean[tid] * sc;
    }
}

// ---------------- main persistent kernel ----------------
__global__ __launch_bounds__(THREADS, 2)
void stgcn_main(const float* __restrict__ x, float* __restrict__ out)
{
    extern __shared__ char sm[];
    const uint32_t sb = cvta_smem(sm);
    const int tid = threadIdx.x, wid = tid >> 5, lane = tid & 31;

    // one-time: copy constants (no pad-zeroing needed: every U byte read is
    // rewritten every item; PA/W pads zeroed in setup)
    {
        for (int i = tid; i < 480; i += THREADS)
            ((uint4*)(sm + OFF_PA))[i] = ((const uint4*)gPA)[i];
        for (int i = tid; i < 1728; i += THREADS)
            ((uint4*)(sm + OFF_W))[i] = ((const uint4*)gW)[i];
        for (int i = tid; i < 400; i += THREADS)
            ((uint4*)(sm + OFF_ZB))[i] = ((const uint4*)gZb)[i];
        if (tid < 64) {
            ((float*)(sm + OFF_BN))[tid]      = gScale[tid];
            ((float*)(sm + OFF_BN))[64 + tid] = gShift[tid];
        }
    }

    const int mt  = wid & 7, ng  = wid >> 3;   // stage-1 roles (8 x 2)
    const int mt2 = wid & 3, ng2 = wid >> 2;   // stage-2 roles (4 x 4)

    // X-fill per-thread invariants: row0 = tid>>5 (0..15), v = tid&31
    const int frow0 = tid >> 5, fv = tid & 31;
    const int ft = frow0 & 1, fc0 = frow0 >> 1;
    const int fvalid = (fv < 25);
    const int fvc = fvalid ? fv : 24;                  // clamp keeps LDG in-bounds
    const int fsoff = OFF_X + frow0*80 + fv*2;         // += 1280 per k (row += 16)

    // epilogue per-thread invariants (stage-2 fragment mapping, M rows r'=t*32+w)
    const int erb = mt2*16 + (lane >> 2);
    const int eob = ng2*16 + 2*(lane & 3);

    // stage1: u_s = X * PA_s (M=128,K=32,N=32); scatter half2 into U^T[c][t*32+w]
    auto stage1 = [&](int s, int usOff, const uint32_t Ah[2][4]) {
        uint32_t Bh[2][4];
        #pragma unroll
        for (int k16 = 0; k16 < 2; k16++)
            LDSM_X4T(Bh[k16], lm_addr(sb + OFF_PA, s*32 + k16*16, ng*32, 80, lane));
        float acc[2][4];
        #pragma unroll
        for (int j = 0; j < 2; j++)
            #pragma unroll
            for (int e = 0; e < 4; e++) acc[j][e] = 0.f;
        #pragma unroll
        for (int k16 = 0; k16 < 2; k16++)
            #pragma unroll
            for (int j = 0; j < 2; j++)
                MMA(acc[j], Ah[k16][0], Ah[k16][1], Ah[k16][2], Ah[k16][3],
                    Bh[k16][j*2], Bh[k16][j*2+1]);
        // unconditional half2 scatter: w>=25 values are exact zeros (PA pads)
        #pragma unroll
        for (int j = 0; j < 2; j++)
            #pragma unroll
            for (int half = 0; half < 2; half++) {
                int grow = mt*16 + (lane >> 2) + half*8;   // X row = c*2+t
                int c = grow >> 1, t = grow & 1;
                int col = t*32 + ng*16 + j*8 + 2*(lane & 3);
                __half2 hv = __floats2half2_rn(acc[j][half*2], acc[j][half*2+1]);
                *(__half2*)(sm + usOff + c*144 + col*2) = hv;
            }
    };
    // stage2: zacc += U^T(trans-A) * W_s^T (M=64 r', K=64 c, N=64 o)
    auto stage2 = [&](int s, int usOff, float zacc[2][4]) {
        #pragma unroll
        for (int k16 = 0; k16 < 4; k16++) {
            uint32_t Au[4], Bw[4];
            LDSM_X4T(Au, lm_addr(sb + usOff, k16*16, mt2*32, 144, lane));
            LDSM_X4T(Bw, lm_addr(sb + OFF_W, s*64 + k16*16, ng2*32, 144, lane));
            #pragma unroll
            for (int j = 0; j < 2; j++)       // trans-A order: a0,a2,a1,a3
                MMA(zacc[j], Au[0], Au[2], Au[1], Au[3], Bw[j*2], Bw[j*2+1]);
        }
    };

    for (int item = blockIdx.x; item < ITEMS; item += CTAS) {
        const int b = item & 63, tile = item >> 6;
        const int n = b >> 1, m = b & 1, t0 = tile * 2;

        // fill X fp16 — hoisted addressing, 8 x (LDG, CVT, STS)
        {
            long long gbase = (((long long)(n*64 + fc0)*300 + (t0 + ft))*25 + fvc)*2 + m;
            #pragma unroll
            for (int k = 0; k < 8; k++) {
                float xv = x[gbase + (long long)k*120000];
                __half hv = fvalid ? __float2half_rn(xv) : __float2half(0.f);
                *(__half*)(sm + fsoff + k*1280) = hv;
            }
        }
        __syncthreads();                       // barB: X ready; prev US0 reads done

        uint32_t Ah[2][4];
        #pragma unroll
        for (int k16 = 0; k16 < 2; k16++)
            LDSM_X4(Ah[k16], lm_addr(sb + OFF_X, mt*16, k16*32, 80, lane));

        float zacc[2][4];
        #pragma unroll
        for (int j = 0; j < 2; j++)
            #pragma unroll
            for (int e = 0; e < 4; e++) zacc[j][e] = 0.f;

        stage1(0, OFF_US0, Ah);
        __syncthreads();                       // barC: US0 ready
        stage1(1, OFF_US1, Ah);
        stage2(0, OFF_US0, zacc);
        __syncthreads();                       // barD: US1 ready, US0 reads done
        stage1(2, OFF_US0, Ah);
        stage2(1, OFF_US1, zacc);
        __syncthreads();                       // barE: US0(2) ready, US1 reads done
        stage2(2, OFF_US0, zacc);

        // epilogue: direct from fragments — BN + relu + residual + relu + store
        {
            const float* zbS = (const float*)(sm + OFF_ZB);
            const float* scS = (const float*)(sm + OFF_BN);
            const float* shS = scS + 64;
            const long long gb = (long long)n*960000 + t0*50 + m;
            #pragma unroll
            for (int half = 0; half < 2; half++) {
                int rp = erb + half*8;         // r' = t*32 + w
                int t = rp >> 5, w = rp & 31;
                if (w < 25) {
                    long long gtw = gb + t*50 + w*2;
                    #pragma unroll
                    for (int j = 0; j < 2; j++)
                        #pragma unroll
                        for (int e = 0; e < 2; e++) {
                            int o = eob + j*8 + e;
                            float z = zacc[j][half*2 + e] + zbS[o*25 + w];
                            float zn = fmaxf(fmaf(z, scS[o], shS[o]), 0.f);
                            long long gi = gtw + o*15000;
                            out[gi] = fmaxf(zn + x[gi], 0.f);
                        }
                }
            }
        }
    }
}

extern "C" void kernel_launch(void* const* d_in, const int* in_sizes, int n_in,
                              void* d_out, int out_size)
{
    const float* x     = (const float*)d_in[0];
    const float* PA    = (const float*)d_in[1];
    const float* Wc    = (const float*)d_in[2];
    const float* bc    = (const float*)d_in[3];
    const float* gamma = (const float*)d_in[4];
    const float* beta  = (const float*)d_in[5];
    const float* mean  = (const float*)d_in[6];
    const float* var   = (const float*)d_in[7];

    setup_kernel<<<1, 512>>>(PA, Wc, bc, gamma, beta, mean, var);

    cudaFuncSetAttribute(stgcn_main, cudaFuncAttributeMaxDynamicSharedMemorySize, SMEM_TOTAL);
    stgcn_main<<<CTAS, THREADS, SMEM_TOTAL>>>(x, (float*)d_out);
}

// round 14
// speedup vs baseline: 4.2995x; 1.0388x over previous
#include <cuda_runtime.h>
#include <cuda_fp16.h>
#include <stdint.h>

#define THREADS 512
#define CTAS 296            // 2 per SM
#define ITEMS 4800          // 64 batch * 75 T-tiles (TTILE=4)

// Precomputed constant images (plain fp16, R6-proven layouts)
__device__ __align__(16) __half gPA[96*40];    // rows s*32+v, cols w, 80B stride
__device__ __align__(16) __half gW[192*72];    // rows k=(s*64+c), cols o, 144B stride
__device__ __align__(16) float gZb[1600];
__device__ __align__(16) float gScale[64], gShift[64];

// smem byte offsets
#define OFF_X    0          // X: 256 rows (c*4+t) x 80B fp16
#define OFF_PA   20480      // 96 x 80
#define OFF_W    28160      // 192 x 144
#define OFF_US0  55808      // U^T: 64 rows (c) x 272B (136 el; cols r'=t*32+w, t<4)
#define OFF_US1  73216
#define OFF_ZB   90624      // 1600 f32
#define OFF_BN   97024      // 64+64 f32
#define SMEM_TOTAL 97536

#define LDSM_X4(r, a) \
    asm volatile("ldmatrix.sync.aligned.m8n8.x4.shared.b16 {%0,%1,%2,%3}, [%4];" \
        : "=r"((r)[0]), "=r"((r)[1]), "=r"((r)[2]), "=r"((r)[3]) : "r"(a))
#define LDSM_X4T(r, a) \
    asm volatile("ldmatrix.sync.aligned.m8n8.x4.trans.shared.b16 {%0,%1,%2,%3}, [%4];" \
        : "=r"((r)[0]), "=r"((r)[1]), "=r"((r)[2]), "=r"((r)[3]) : "r"(a))
#define MMA(acc, a0, a1, a2, a3, b0, b1) \
    asm volatile("mma.sync.aligned.m16n8k16.row.col.f32.f16.f16.f32 " \
        "{%0,%1,%2,%3}, {%4,%5,%6,%7}, {%8,%9}, {%0,%1,%2,%3};" \
        : "+f"((acc)[0]), "+f"((acc)[1]), "+f"((acc)[2]), "+f"((acc)[3]) \
        : "r"(a0), "r"(a1), "r"(a2), "r"(a3), "r"(b0), "r"(b1))

__device__ __forceinline__ uint32_t cvta_smem(const void* p) {
    uint32_t a;
    asm("{ .reg .u64 t; cvta.to.shared.u64 t, %1; cvt.u32.u64 %0, t; }" : "=r"(a) : "l"(p));
    return a;
}
// R6-proven ldmatrix addressing (padded stride, no swizzle); base is SHARED-space addr
__device__ __forceinline__ uint32_t lm_addr(uint32_t base, int row0, int colByte,
                                            int stride, int lane) {
    return base + (uint32_t)((row0 + (lane & 15)) * stride + colByte + (lane >> 4) * 16);
}

// ---------------- setup ----------------
__global__ void setup_kernel(const float* __restrict__ PA, const float* __restrict__ Wc,
                             const float* __restrict__ bc, const float* __restrict__ gamma,
                             const float* __restrict__ beta, const float* __restrict__ mean,
                             const float* __restrict__ var)
{
    const int tid = threadIdx.x;
    __half z = __float2half(0.f);
    for (int i = tid; i < 96*40;  i += 512) gPA[i] = z;
    for (int i = tid; i < 192*72; i += 512) gW[i]  = z;
    __syncthreads();
    for (int i = tid; i < 1875; i += 512) {       // PA rows s*32+v, cols w
        int s = i / 625, r = i - s*625, v = r / 25, w = r - v*25;
        gPA[(s*32 + v)*40 + w] = __float2half_rn(PA[i]);
    }
    for (int i = tid; i < 192*64; i += 512) {     // W rows k=s*64+c, cols o
        int so = i >> 6, c = i & 63, s = so >> 6, o = so & 63;
        gW[(s*64 + c)*72 + o] = __float2half_rn(Wc[i]);
    }
    for (int i = tid; i < 1600; i += 512) {
        int o = i / 25, w = i - o*25;
        float acc = 0.f;
        for (int s = 0; s < 3; s++) {
            float cs = 0.f;
            for (int v = 0; v < 25; v++) cs += PA[s*625 + v*25 + w];
            acc += bc[s*64 + o] * cs;
        }
        gZb[i] = acc;
    }
    if (tid < 64) {
        float sc = gamma[tid] * rsqrtf(var[tid] + 1e-5f);
        gScale[tid] = sc; gShift[tid] = beta[tid] - mean[tid] * sc;
    }
}

// ---------------- main persistent kernel ----------------
__global__ __launch_bounds__(THREADS, 2)
void stgcn_main(const float* __restrict__ x, float* __restrict__ out)
{
    extern __shared__ char sm[];
    const uint32_t sb = cvta_smem(sm);
    const int tid = threadIdx.x, wid = tid >> 5, lane = tid & 31;

    // one-time: copy constants (every U/X byte read is rewritten every item)
    {
        for (int i = tid; i < 480; i += THREADS)
            ((uint4*)(sm + OFF_PA))[i] = ((const uint4*)gPA)[i];
        for (int i = tid; i < 1728; i += THREADS)
            ((uint4*)(sm + OFF_W))[i] = ((const uint4*)gW)[i];
        for (int i = tid; i < 400; i += THREADS)
            ((uint4*)(sm + OFF_ZB))[i] = ((const uint4*)gZb)[i];
        if (tid < 64) {
            ((float*)(sm + OFF_BN))[tid]      = gScale[tid];
            ((float*)(sm + OFF_BN))[64 + tid] = gShift[tid];
        }
    }

    const int mt  = wid;                        // stage-1: 16 warps x 16 M-rows
    const int mt2 = wid & 7, ng2 = wid >> 3;    // stage-2: 8 x 16 M-rows, 2 x 32 N-cols

    // X-fill invariants: row = frow0 + 16k -> t const, c = fc0 + 4k
    const int frow0 = tid >> 5, fv = tid & 31;
    const int ft = frow0 & 3, fc0 = frow0 >> 2;
    const int fvalid = (fv < 25);
    const int fvc = fvalid ? fv : 24;
    const int fsoff = OFF_X + frow0*80 + fv*2;       // += 1280 per k

    // epilogue invariants
    const int erb = mt2*16 + (lane >> 2);
    const int eob = ng2*32 + 2*(lane & 3);

    // stage1: u_s = X * PA_s (M=256,K=32,N=32); scatter half2 into U^T[c][t*32+w]
    auto stage1 = [&](int s, int usOff, const uint32_t Ah[2][4]) {
        uint32_t Bh[2][2][4];
        #pragma unroll
        for (int k16 = 0; k16 < 2; k16++)
            #pragma unroll
            for (int nh = 0; nh < 2; nh++)
                LDSM_X4T(Bh[k16][nh],
                         lm_addr(sb + OFF_PA, s*32 + k16*16, nh*32, 80, lane));
        float acc[4][4];
        #pragma unroll
        for (int j = 0; j < 4; j++)
            #pragma unroll
            for (int e = 0; e < 4; e++) acc[j][e] = 0.f;
        #pragma unroll
        for (int k16 = 0; k16 < 2; k16++)
            #pragma unroll
            for (int j = 0; j < 4; j++)
                MMA(acc[j], Ah[k16][0], Ah[k16][1], Ah[k16][2], Ah[k16][3],
                    Bh[k16][j>>1][(j&1)*2], Bh[k16][j>>1][(j&1)*2+1]);
        // unconditional half2 scatter (w>=25 are exact zeros from PA pads)
        #pragma unroll
        for (int half = 0; half < 2; half++) {
            int grow = mt*16 + (lane >> 2) + half*8;   // X row = c*4+t
            int c = grow >> 2, t = grow & 3;
            int base = usOff + c*272 + (t*32 + 2*(lane & 3))*2;
            #pragma unroll
            for (int j = 0; j < 4; j++) {
                __half2 hv = __floats2half2_rn(acc[j][half*2], acc[j][half*2+1]);
                *(__half2*)(sm + base + j*16) = hv;
            }
        }
    };
    // stage2: zacc += U^T(trans-A) * W_s^T (M=128 r', K=64 c, N=64 o)
    auto stage2 = [&](int s, int usOff, float zacc[4][4]) {
        #pragma unroll
        for (int k16 = 0; k16 < 4; k16++) {
            uint32_t Au[4], Bw[2][4];
            LDSM_X4T(Au, lm_addr(sb + usOff, k16*16, mt2*32, 272, lane));
            #pragma unroll
            for (int nh = 0; nh < 2; nh++)
                LDSM_X4T(Bw[nh],
                         lm_addr(sb + OFF_W, s*64 + k16*16, ng2*64 + nh*32, 144, lane));
            #pragma unroll
            for (int j = 0; j < 4; j++)       // trans-A order: a0,a2,a1,a3
                MMA(zacc[j], Au[0], Au[2], Au[1], Au[3],
                    Bw[j>>1][(j&1)*2], Bw[j>>1][(j&1)*2+1]);
        }
    };

    for (int item = blockIdx.x; item < ITEMS; item += CTAS) {
        const int b = item & 63, tile = item >> 6;
        const int n = b >> 1, m = b & 1, t0 = tile * 4;

        // fill X fp16 — hoisted addressing, 16 x (LDG, CVT, STS)
        {
            long long gbase = (((long long)(n*64 + fc0)*300 + (t0 + ft))*25 + fvc)*2 + m;
            #pragma unroll
            for (int k = 0; k < 16; k++) {
                float xv = x[gbase + (long long)k*60000];
                __half hv = fvalid ? __float2half_rn(xv) : __float2half(0.f);
                *(__half*)(sm + fsoff + k*1280) = hv;
            }
        }
        __syncthreads();                       // barB: X ready; prev US0 reads done

        uint32_t Ah[2][4];
        #pragma unroll
        for (int k16 = 0; k16 < 2; k16++)
            LDSM_X4(Ah[k16], lm_addr(sb + OFF_X, mt*16, k16*32, 80, lane));

        float zacc[4][4];
        #pragma unroll
        for (int j = 0; j < 4; j++)
            #pragma unroll
            for (int e = 0; e < 4; e++) zacc[j][e] = 0.f;

        stage1(0, OFF_US0, Ah);
        __syncthreads();                       // barC: US0 ready
        stage1(1, OFF_US1, Ah);
        stage2(0, OFF_US0, zacc);
        __syncthreads();                       // barD: US1 ready, US0 reads done
        stage1(2, OFF_US0, Ah);
        stage2(1, OFF_US1, zacc);
        __syncthreads();                       // barE: US0(2) ready, US1 reads done
        stage2(2, OFF_US0, zacc);

        // epilogue: BN + relu + residual(smem X, fp16) + relu + store
        {
            const float* zbS = (const float*)(sm + OFF_ZB);
            const float* scS = (const float*)(sm + OFF_BN);
            const float* shS = scS + 64;
            const long long gb = (long long)n*960000 + t0*50 + m;
            #pragma unroll
            for (int half = 0; half < 2; half++) {
                int rp = erb + half*8;         // r' = t*32 + w
                int t = rp >> 5, w = rp & 31;
                if (w < 25) {
                    long long gtw = gb + t*50 + w*2;
                    #pragma unroll
                    for (int j = 0; j < 4; j++)
                        #pragma unroll
                        for (int e = 0; e < 2; e++) {
                            int o = eob + j*8 + e;
                            float z = zacc[j][half*2 + e] + zbS[o*25 + w];
                            float zn = fmaxf(fmaf(z, scS[o], shS[o]), 0.f);
                            float res = __half2float(
                                *(const __half*)(sm + OFF_X + (o*4 + t)*80 + w*2));
                            out[gtw + o*15000] = fmaxf(zn + res, 0.f);
                        }
                }
            }
        }
        __syncthreads();                       // barTop: X residual reads done
    }
}

extern "C" void kernel_launch(void* const* d_in, const int* in_sizes, int n_in,
                              void* d_out, int out_size)
{
    const float* x     = (const float*)d_in[0];
    const float* PA    = (const float*)d_in[1];
    const float* Wc    = (const float*)d_in[2];
    const float* bc    = (const float*)d_in[3];
    const float* gamma = (const float*)d_in[4];
    const float* beta  = (const float*)d_in[5];
    const float* mean  = (const float*)d_in[6];
    const float* var   = (const float*)d_in[7];

    setup_kernel<<<1, 512>>>(PA, Wc, bc, gamma, beta, mean, var);

    cudaFuncSetAttribute(stgcn_main, cudaFuncAttributeMaxDynamicSharedMemorySize, SMEM_TOTAL);
    stgcn_main<<<CTAS, THREADS, SMEM_TOTAL>>>(x, (float*)d_out);
}

// round 16
// speedup vs baseline: 4.3819x; 1.0192x over previous
#include <cuda_runtime.h>
#include <cuda_fp16.h>
#include <stdint.h>
#include <string.h>

#define THREADS 512
#define CTAS 296            // 2 per SM
#define ITEMS 4800          // 64 batch * 75 T-tiles (TTILE=4)

// Precomputed constant images (plain fp16, R6-proven layouts)
__device__ __align__(16) __half gPA[96*40];    // rows s*32+v, cols w, 80B stride
__device__ __align__(16) __half gW[192*72];    // rows k=(s*64+c), cols o, 144B stride
__device__ __align__(16) float gZb[1600];
__device__ __align__(16) float gScale[64], gShift[64];

// smem byte offsets (X region removed — A-frags come straight from global)
#define OFF_PA   0          // 96 x 80
#define OFF_W    7680       // 192 x 144
#define OFF_US0  35328      // U^T: 64 rows (c) x 272B (cols r'=t*32+w, t<4)
#define OFF_US1  52736
#define OFF_ZB   70144      // 1600 f32
#define OFF_BN   76544      // 64+64 f32
#define SMEM_TOTAL 77056

#define LDSM_X4T(r, a) \
    asm volatile("ldmatrix.sync.aligned.m8n8.x4.trans.shared.b16 {%0,%1,%2,%3}, [%4];" \
        : "=r"((r)[0]), "=r"((r)[1]), "=r"((r)[2]), "=r"((r)[3]) : "r"(a))
#define MMA(acc, a0, a1, a2, a3, b0, b1) \
    asm volatile("mma.sync.aligned.m16n8k16.row.col.f32.f16.f16.f32 " \
        "{%0,%1,%2,%3}, {%4,%5,%6,%7}, {%8,%9}, {%0,%1,%2,%3};" \
        : "+f"((acc)[0]), "+f"((acc)[1]), "+f"((acc)[2]), "+f"((acc)[3]) \
        : "r"(a0), "r"(a1), "r"(a2), "r"(a3), "r"(b0), "r"(b1))

__device__ __forceinline__ uint32_t cvta_smem(const void* p) {
    uint32_t a;
    asm("{ .reg .u64 t; cvta.to.shared.u64 t, %1; cvt.u32.u64 %0, t; }" : "=r"(a) : "l"(p));
    return a;
}
__device__ __forceinline__ uint32_t h2_bits(__half2 h) {
    uint32_t u; memcpy(&u, &h, 4); return u;
}
// R6-proven ldmatrix addressing (padded stride, no swizzle); base is SHARED-space addr
__device__ __forceinline__ uint32_t lm_addr(uint32_t base, int row0, int colByte,
                                            int stride, int lane) {
    return base + (uint32_t)((row0 + (lane & 15)) * stride + colByte + (lane >> 4) * 16);
}

// ---------------- setup ----------------
__global__ void setup_kernel(const float* __restrict__ PA, const float* __restrict__ Wc,
                             const float* __restrict__ bc, const float* __restrict__ gamma,
                             const float* __restrict__ beta, const float* __restrict__ mean,
                             const float* __restrict__ var)
{
    const int tid = threadIdx.x;
    __half z = __float2half(0.f);
    for (int i = tid; i < 96*40;  i += 512) gPA[i] = z;
    for (int i = tid; i < 192*72; i += 512) gW[i]  = z;
    __syncthreads();
    for (int i = tid; i < 1875; i += 512) {       // PA rows s*32+v, cols w
        int s = i / 625, r = i - s*625, v = r / 25, w = r - v*25;
        gPA[(s*32 + v)*40 + w] = __float2half_rn(PA[i]);
    }
    for (int i = tid; i < 192*64; i += 512) {     // W rows k=s*64+c, cols o
        int so = i >> 6, c = i & 63, s = so >> 6, o = so & 63;
        gW[(s*64 + c)*72 + o] = __float2half_rn(Wc[i]);
    }
    for (int i = tid; i < 1600; i += 512) {
        int o = i / 25, w = i - o*25;
        float acc = 0.f;
        for (int s = 0; s < 3; s++) {
            float cs = 0.f;
            for (int v = 0; v < 25; v++) cs += PA[s*625 + v*25 + w];
            acc += bc[s*64 + o] * cs;
        }
        gZb[i] = acc;
    }
    if (tid < 64) {
        float sc = gamma[tid] * rsqrtf(var[tid] + 1e-5f);
        gScale[tid] = sc; gShift[tid] = beta[tid] - mean[tid] * sc;
    }
}

// ---------------- main persistent kernel ----------------
__global__ __launch_bounds__(THREADS, 2)
void stgcn_main(const float* __restrict__ x, float* __restrict__ out)
{
    extern __shared__ char sm[];
    const uint32_t sb = cvta_smem(sm);
    const int tid = threadIdx.x, wid = tid >> 5, lane = tid & 31;

    // one-time: copy constants (every U byte read is rewritten every item)
    {
        for (int i = tid; i < 480; i += THREADS)
            ((uint4*)(sm + OFF_PA))[i] = ((const uint4*)gPA)[i];
        for (int i = tid; i < 1728; i += THREADS)
            ((uint4*)(sm + OFF_W))[i] = ((const uint4*)gW)[i];
        for (int i = tid; i < 400; i += THREADS)
            ((uint4*)(sm + OFF_ZB))[i] = ((const uint4*)gZb)[i];
        if (tid < 64) {
            ((float*)(sm + OFF_BN))[tid]      = gScale[tid];
            ((float*)(sm + OFF_BN))[64 + tid] = gShift[tid];
        }
    }

    const int mt  = wid;                        // stage-1: 16 warps x 16 M-rows
    const int mt2 = wid & 7, ng2 = wid >> 3;    // stage-2: 8 x 16 M-rows, 2 x 32 N-cols

    // A-frag per-thread invariants (from the proven non-trans ldmatrix lane map):
    // reg 2*khalf+mhalf; lane L -> row = L>>2 (+8*mhalf), k = 2*(L&3)+e (+8*khalf)
    const int arow = mt*16 + (lane >> 2);       // X row = c*4+t
    const int aca = arow >> 2, ata = arow & 3;  // row+8 -> c+2, same t
    const int av  = (lane & 3) * 2;

    // epilogue invariants
    const int erb = mt2*16 + (lane >> 2);
    const int eob = ng2*32 + 2*(lane & 3);

    // stage1: u_s = X * PA_s (M=256,K=32,N=32); scatter half2 into U^T[c][t*32+w]
    auto stage1 = [&](int s, int usOff, const uint32_t Ah[2][4]) {
        uint32_t Bh[2][2][4];
        #pragma unroll
        for (int k16 = 0; k16 < 2; k16++)
            #pragma unroll
            for (int nh = 0; nh < 2; nh++)
                LDSM_X4T(Bh[k16][nh],
                         lm_addr(sb + OFF_PA, s*32 + k16*16, nh*32, 80, lane));
        float acc[4][4];
        #pragma unroll
        for (int j = 0; j < 4; j++)
            #pragma unroll
            for (int e = 0; e < 4; e++) acc[j][e] = 0.f;
        #pragma unroll
        for (int k16 = 0; k16 < 2; k16++)
            #pragma unroll
            for (int j = 0; j < 4; j++)
                MMA(acc[j], Ah[k16][0], Ah[k16][1], Ah[k16][2], Ah[k16][3],
                    Bh[k16][j>>1][(j&1)*2], Bh[k16][j>>1][(j&1)*2+1]);
        // unconditional half2 scatter (w>=25 are exact zeros from PA pads)
        #pragma unroll
        for (int half = 0; half < 2; half++) {
            int grow = mt*16 + (lane >> 2) + half*8;   // row = c*4+t
            int c = grow >> 2, t = grow & 3;
            int base = usOff + c*272 + (t*32 + 2*(lane & 3))*2;
            #pragma unroll
            for (int j = 0; j < 4; j++) {
                __half2 hv = __floats2half2_rn(acc[j][half*2], acc[j][half*2+1]);
                *(__half2*)(sm + base + j*16) = hv;
            }
        }
    };
    // stage2: zacc += U^T(trans-A) * W_s^T (M=128 r', K=64 c, N=64 o)
    auto stage2 = [&](int s, int usOff, float zacc[4][4]) {
        #pragma unroll
        for (int k16 = 0; k16 < 4; k16++) {
            uint32_t Au[4], Bw[2][4];
            LDSM_X4T(Au, lm_addr(sb + usOff, k16*16, mt2*32, 272, lane));
            #pragma unroll
            for (int nh = 0; nh < 2; nh++)
                LDSM_X4T(Bw[nh],
                         lm_addr(sb + OFF_W, s*64 + k16*16, ng2*64 + nh*32, 144, lane));
            #pragma unroll
            for (int j = 0; j < 4; j++)       // trans-A order: a0,a2,a1,a3
                MMA(zacc[j], Au[0], Au[2], Au[1], Au[3],
                    Bw[j>>1][(j&1)*2], Bw[j>>1][(j&1)*2+1]);
        }
    };

    for (int item = blockIdx.x; item < ITEMS; item += CTAS) {
        const int b = item & 63, tile = item >> 6;
        const int n = b >> 1, m = b & 1, t0 = tile * 4;

        // build A-fragments directly from global x (16 LDG + 8 packs, no smem)
        uint32_t Ah[2][4];
        {
            const long long ga = (long long)n*960000 + aca*15000 + (t0 + ata)*50 + m;
            const long long gb2 = ga + 30000;          // row+8 -> c+2
            #pragma unroll
            for (int k16 = 0; k16 < 2; k16++)
                #pragma unroll
                for (int kh = 0; kh < 2; kh++) {
                    int v0 = k16*16 + kh*8 + av, v1 = v0 + 1;
                    int o0 = (v0 < 25 ? v0 : 24)*2, o1 = (v1 < 25 ? v1 : 24)*2;
                    float a0 = (v0 < 25) ? x[ga  + o0] : 0.f;
                    float a1 = (v1 < 25) ? x[ga  + o1] : 0.f;
                    float b0 = (v0 < 25) ? x[gb2 + o0] : 0.f;
                    float b1 = (v1 < 25) ? x[gb2 + o1] : 0.f;
                    Ah[k16][2*kh + 0] = h2_bits(__floats2half2_rn(a0, a1));
                    Ah[k16][2*kh + 1] = h2_bits(__floats2half2_rn(b0, b1));
                }
        }
        __syncthreads();                       // barTop: prev US0 reads done

        float zacc[4][4];
        #pragma unroll
        for (int j = 0; j < 4; j++)
            #pragma unroll
            for (int e = 0; e < 4; e++) zacc[j][e] = 0.f;

        stage1(0, OFF_US0, Ah);
        __syncthreads();                       // barC: US0 ready
        stage1(1, OFF_US1, Ah);
        stage2(0, OFF_US0, zacc);
        __syncthreads();                       // barD: US1 ready, US0 reads done
        stage1(2, OFF_US0, Ah);
        stage2(1, OFF_US1, zacc);
        __syncthreads();                       // barE: US0(2) ready, US1 reads done
        stage2(2, OFF_US0, zacc);

        // epilogue: BN + relu + residual(global, exact) + relu + store
        {
            const float* zbS = (const float*)(sm + OFF_ZB);
            const float* scS = (const float*)(sm + OFF_BN);
            const float* shS = scS + 64;
            const long long gb = (long long)n*960000 + t0*50 + m;
            #pragma unroll
            for (int half = 0; half < 2; half++) {
                int rp = erb + half*8;         // r' = t*32 + w
                int t = rp >> 5, w = rp & 31;
                if (w < 25) {
                    long long gtw = gb + t*50 + w*2;
                    #pragma unroll
                    for (int j = 0; j < 4; j++)
                        #pragma unroll
                        for (int e = 0; e < 2; e++) {
                            int o = eob + j*8 + e;
                            float z = zacc[j][half*2 + e] + zbS[o*25 + w];
                            float zn = fmaxf(fmaf(z, scS[o], shS[o]), 0.f);
                            long long gi = gtw + o*15000;
                            out[gi] = fmaxf(zn + x[gi], 0.f);
                        }
                }
            }
        }
    }
}

extern "C" void kernel_launch(void* const* d_in, const int* in_sizes, int n_in,
                              void* d_out, int out_size)
{
    const float* x     = (const float*)d_in[0];
    const float* PA    = (const float*)d_in[1];
    const float* Wc    = (const float*)d_in[2];
    const float* bc    = (const float*)d_in[3];
    const float* gamma = (const float*)d_in[4];
    const float* beta  = (const float*)d_in[5];
    const float* mean  = (const float*)d_in[6];
    const float* var   = (const float*)d_in[7];

    setup_kernel<<<1, 512>>>(PA, Wc, bc, gamma, beta, mean, var);

    cudaFuncSetAttribute(stgcn_main, cudaFuncAttributeMaxDynamicSharedMemorySize, SMEM_TOTAL);
    stgcn_main<<<CTAS, THREADS, SMEM_TOTAL>>>(x, (float*)d_out);
}